// round 5
// baseline (speedup 1.0000x reference)
#include <cuda_runtime.h>

// ---------------------------------------------------------------------------
// NeuralODE (Dopri5, piecewise-constant actions) — fp32 SIMT, round 4.
// 128 CTAs x 512 threads. CTA split into TWO INDEPENDENT 256-thread halves
// (named barriers): half g owns batch rows 4g..4g+3 end-to-end. When one
// half stalls (barrier / L2 weight latency) the other half's 8 warps issue.
// Hidden layers: thread = 1 col x 4 rows, LDG.32 coalesced weights,
// broadcast LDS.128 activations.
// (Round 4 = Round 3 resubmit minus a racy placeholder write in sidx.)
// ---------------------------------------------------------------------------

#define B_    1024
#define T_    64
#define OB_   64
#define AC_   16
#define AUG_  32
#define H_    256
#define IN_   112   // OB + AC + AUG
#define OUT_  96    // OB + AUG
#define RH_   4     // rows per half
#define R_    8     // rows per CTA (2 halves)
#define NCTA  (B_ / R_)   // 128
#define NTHR  512

__device__ float g_W0t[IN_ * H_];     // [k<112][j<256]
__device__ float g_W1t[H_ * H_];      // [k<256][j<256]
__device__ float g_W2t[H_ * H_];
__device__ float g_W3t[H_ * 128];     // [k<256][j<128], cols 96..127 zero

__constant__ float cAT[6][5] = {
    {0.f, 0.f, 0.f, 0.f, 0.f},
    {1.0f / 5.0f, 0.f, 0.f, 0.f, 0.f},
    {3.0f / 40.0f, 9.0f / 40.0f, 0.f, 0.f, 0.f},
    {44.0f / 45.0f, -56.0f / 15.0f, 32.0f / 9.0f, 0.f, 0.f},
    {19372.0f / 6561.0f, -25360.0f / 2187.0f, 64448.0f / 6561.0f, -212.0f / 729.0f, 0.f},
    {9017.0f / 3168.0f, -355.0f / 33.0f, 46732.0f / 5247.0f, 49.0f / 176.0f, -5103.0f / 18656.0f}
};
__constant__ float cB[6] = {
    35.0f / 384.0f, 0.0f, 500.0f / 1113.0f, 125.0f / 192.0f,
    -2187.0f / 6784.0f, 11.0f / 84.0f
};

__global__ void transpose_k(const float* __restrict__ W0, const float* __restrict__ W1,
                            const float* __restrict__ W2, const float* __restrict__ W3) {
    int i = blockIdx.x * blockDim.x + threadIdx.x;   // 65536 threads
    if (i < H_ * IN_)  { int j = i / IN_, k = i % IN_;  g_W0t[k * H_ + j] = W0[i]; }
    if (i < H_ * H_)   { int j = i >> 8, k = i & 255;   g_W1t[k * H_ + j] = W1[i];
                                                        g_W2t[k * H_ + j] = W2[i]; }
    if (i < H_ * 128)  { int k = i >> 7, j = i & 127;
                         g_W3t[k * 128 + j] = (j < OUT_) ? W3[j * H_ + k] : 0.0f; }
}

#define HBAR(hh) asm volatile("bar.sync %0, 256;" :: "r"((hh) + 1) : "memory")

// Hidden layer: 4 rows, 256 cols, thread = 1 col x 4 rows.
__device__ __forceinline__ void layer_h(const float* __restrict__ Wt,
                                        const float* __restrict__ xin, int xs, int Kq,
                                        float bias, float* __restrict__ xout,
                                        int col) {
    const float* wp = Wt + col;
    float a0 = 0.f, a1 = 0.f, a2 = 0.f, a3 = 0.f;
#pragma unroll 4
    for (int k4 = 0; k4 < Kq; ++k4) {
        const int k = k4 * 4;
        const float w0 = wp[(k + 0) * H_];
        const float w1 = wp[(k + 1) * H_];
        const float w2 = wp[(k + 2) * H_];
        const float w3 = wp[(k + 3) * H_];
        const float4 x0 = *(const float4*)(xin + 0 * xs + k);
        const float4 x1 = *(const float4*)(xin + 1 * xs + k);
        const float4 x2 = *(const float4*)(xin + 2 * xs + k);
        const float4 x3 = *(const float4*)(xin + 3 * xs + k);
        a0 += w0 * x0.x; a0 += w1 * x0.y; a0 += w2 * x0.z; a0 += w3 * x0.w;
        a1 += w0 * x1.x; a1 += w1 * x1.y; a1 += w2 * x1.z; a1 += w3 * x1.w;
        a2 += w0 * x2.x; a2 += w1 * x2.y; a2 += w2 * x2.z; a2 += w3 * x2.w;
        a3 += w0 * x3.x; a3 += w1 * x3.y; a3 += w2 * x3.z; a3 += w3 * x3.w;
    }
    xout[0 * H_ + col] = fmaxf(a0 + bias, 0.f);
    xout[1 * H_ + col] = fmaxf(a1 + bias, 0.f);
    xout[2 * H_ + col] = fmaxf(a2 + bias, 0.f);
    xout[3 * H_ + col] = fmaxf(a3 + bias, 0.f);
}

// Output layer (N padded to 128, K=256): thread = 1 col x 2 rows.
// warp lw: rows {2*(lw&1), 2*(lw&1)+1}, col = (lw>>1)*32+lane.
__device__ __forceinline__ void layer_o(const float* __restrict__ Wt,
                                        const float* __restrict__ xin,
                                        float bias, float* __restrict__ ks,
                                        int rg, int col) {
    const float* xp = xin + rg * 2 * H_;
    const float* wp = Wt + col;
    float a0 = 0.f, a1 = 0.f;
#pragma unroll 4
    for (int k4 = 0; k4 < H_ / 4; ++k4) {
        const int k = k4 * 4;
        const float w0 = wp[(k + 0) * 128];
        const float w1 = wp[(k + 1) * 128];
        const float w2 = wp[(k + 2) * 128];
        const float w3 = wp[(k + 3) * 128];
        const float4 x0 = *(const float4*)(xp + k);
        const float4 x1 = *(const float4*)(xp + H_ + k);
        a0 += w0 * x0.x; a0 += w1 * x0.y; a0 += w2 * x0.z; a0 += w3 * x0.w;
        a1 += w0 * x1.x; a1 += w1 * x1.y; a1 += w2 * x1.z; a1 += w3 * x1.w;
    }
    if (col < OUT_) {
        ks[(rg * 2 + 0) * OUT_ + col] = a0 + bias;
        ks[(rg * 2 + 1) * OUT_ + col] = a1 + bias;
    }
}

__global__ void __launch_bounds__(NTHR, 1)
node_kernel(const float* __restrict__ ob, const float* __restrict__ acs,
            const float* __restrict__ times,
            const float* __restrict__ b0, const float* __restrict__ b1,
            const float* __restrict__ b2, const float* __restrict__ b3,
            float* __restrict__ out) {
    // Per-half shared buffers
    __shared__ __align__(16) float sy  [2][RH_ * OUT_];      // 2 x 384
    __shared__ __align__(16) float sks [2][6 * RH_ * OUT_];  // 2 x 2304
    __shared__ __align__(16) float sxs [2][RH_ * IN_];       // 2 x 448
    __shared__ __align__(16) float shA [2][RH_ * H_];        // 2 x 1024
    __shared__ __align__(16) float shB [2][RH_ * H_];        // 2 x 1024
    __shared__ __align__(16) float sacs[2][12 * RH_ * AC_];  // 2 x 768
    __shared__ float shh [2][RH_];
    __shared__ int   sidx[2][12 * RH_];

    const int tid  = threadIdx.x;
    const int hh   = tid >> 8;          // half id: 0 or 1
    const int ltid = tid & 255;         // tid within half
    const int lw   = ltid >> 5;         // warp within half (0..7)
    const int lane = ltid & 31;
    const int row0 = blockIdx.x * R_ + hh * RH_;   // first global row of half

    // Hidden-layer col (1 col, 4 rows)
    const int colH = lw * 32 + lane;    // 0..255
    const float bh0 = b0[colH];
    const float bh1 = b1[colH];
    const float bh2 = b2[colH];
    // Output-layer mapping
    const int rgO  = lw & 1;
    const int colO = (lw >> 1) * 32 + lane;   // 0..127
    const float bo = (colO < OUT_) ? b3[colO] : 0.0f;

    float* const myy  = sy[hh];
    float* const myks = sks[hh];
    float* const myxs = sxs[hh];
    float* const myA  = shA[hh];
    float* const myB  = shB[hh];
    float* const myac = sacs[hh];

    // y0 = [ob, zeros(AUG)]; emit save slot t=0
    for (int idx = ltid; idx < RH_ * OUT_; idx += 256) {
        int r = idx / OUT_, e = idx - r * OUT_;
        float v = (e < OB_) ? ob[(row0 + r) * OB_ + e] : 0.0f;
        myy[idx] = v;
        if (e < OB_) out[(size_t)(row0 + r) * T_ * OB_ + e] = v;
    }
    HBAR(hh);

    for (int j = 0; j < T_ - 1; j++) {
        // --- interval prologue: per-row h + 12 stage action indices ---
        if (ltid < RH_) {
            const int r = ltid;
            const float* tsr = times + (size_t)(row0 + r) * T_;
            const float t0 = tsr[j], t1 = tsr[j + 1];
            const float h = (t1 - t0) / 2.0f;          // N_SUB = 2
            shh[hh][r] = h;
            for (int sub = 0; sub < 2; sub++) {
                const float t = t0 + (float)sub * h;
                float st[6];
                st[0] = t;
                st[1] = t + h / 5.0f;
                st[2] = t + (3.0f * h) / 10.0f;
                st[3] = t + (4.0f * h) / 5.0f;
                st[4] = t + (8.0f * h) / 9.0f;
                st[5] = t + h;
                for (int s = 0; s < 6; s++) {
                    int cnt = 0;                       // searchsorted(side='right')
                    for (int i = 0; i < T_; i++) cnt += (tsr[i] <= st[s]) ? 1 : 0;
                    int ai = cnt - 1;
                    ai = max(0, min(ai, T_ - 1));
                    sidx[hh][(sub * 6 + s) * RH_ + r] = ai;
                }
            }
        }
        HBAR(hh);
        // Prefetch the 12 action vectors for this interval
        for (int idx = ltid; idx < 12 * RH_ * AC_; idx += 256) {
            int s12 = idx / (RH_ * AC_);
            int rem = idx - s12 * (RH_ * AC_);
            int r = rem >> 4, c = rem & 15;
            myac[idx] = acs[(size_t)(row0 + r) * T_ * AC_ +
                            (size_t)sidx[hh][s12 * RH_ + r] * AC_ + c];
        }
        HBAR(hh);

        for (int sub = 0; sub < 2; sub++) {
            for (int s = 0; s < 6; s++) {
                // Stage input: y + h * sum_i A[s][i] * k_i   (+ action tail)
                for (int idx = ltid; idx < RH_ * OUT_; idx += 256) {
                    int r = idx / OUT_, e = idx - r * OUT_;
                    float x = myy[idx];
                    if (s > 0) {
                        float acc = 0.0f;
                        for (int i = 0; i < s; i++)
                            acc += cAT[s][i] * myks[(i * RH_ + r) * OUT_ + e];
                        x += shh[hh][r] * acc;
                    }
                    myxs[r * IN_ + e] = x;
                }
                if (ltid < RH_ * AC_) {
                    int r = ltid >> 4;
                    myxs[r * IN_ + OUT_ + (ltid & 15)] =
                        myac[(sub * 6 + s) * RH_ * AC_ + ltid];
                }
                HBAR(hh);

                layer_h(g_W0t, myxs, IN_, IN_ / 4, bh0, myA, colH);
                HBAR(hh);
                layer_h(g_W1t, myA, H_, H_ / 4, bh1, myB, colH);
                HBAR(hh);
                layer_h(g_W2t, myB, H_, H_ / 4, bh2, myA, colH);
                HBAR(hh);
                layer_o(g_W3t, myA, bo, myks + s * RH_ * OUT_, rgO, colO);
                HBAR(hh);
            }
            // y += h * sum_i b_i * k_i
            for (int idx = ltid; idx < RH_ * OUT_; idx += 256) {
                int r = idx / OUT_, e = idx - r * OUT_;
                float acc = 0.0f;
                for (int i = 0; i < 6; i++)
                    acc += cB[i] * myks[(i * RH_ + r) * OUT_ + e];
                myy[idx] += shh[hh][r] * acc;
            }
            HBAR(hh);
        }
        // Save observable part at t_{j+1}
        for (int idx = ltid; idx < RH_ * OB_; idx += 256) {
            int r = idx >> 6, c = idx & 63;
            out[(size_t)(row0 + r) * T_ * OB_ + (size_t)(j + 1) * OB_ + c] =
                myy[r * OUT_ + c];
        }
        HBAR(hh);
    }
}

extern "C" void kernel_launch(void* const* d_in, const int* in_sizes, int n_in,
                              void* d_out, int out_size) {
    const float* ob    = (const float*)d_in[0];
    const float* acs   = (const float*)d_in[1];
    const float* times = (const float*)d_in[2];
    const float* W0    = (const float*)d_in[3];
    const float* b0    = (const float*)d_in[4];
    const float* W1    = (const float*)d_in[5];
    const float* b1    = (const float*)d_in[6];
    const float* W2    = (const float*)d_in[7];
    const float* b2    = (const float*)d_in[8];
    const float* W3    = (const float*)d_in[9];
    const float* b3    = (const float*)d_in[10];
    float* out = (float*)d_out;

    transpose_k<<<256, 256>>>(W0, W1, W2, W3);
    node_kernel<<<NCTA, NTHR>>>(ob, acs, times, b0, b1, b2, b3, out);
}

// round 7
// speedup vs baseline: 1.5175x; 1.5175x over previous
#include <cuda_runtime.h>

// ---------------------------------------------------------------------------
// NeuralODE (Dopri5, piecewise-constant actions) — fp32 SIMT, round 6.
// 128 CTAs x 512 threads, 8 rows/CTA, single CTA-wide sync.
// K-SPLIT layers: 512 thr = 128 col-pairs x 4 K-groups; thread = 2 cols x
// 8 rows x K/4. Every weight element loaded ONCE per CTA (LDG.64 coalesced),
// x LDS.128 reused across 2 cols, partial sums reduced via smem (groups 1-3
// spill, group 0 reduces + bias + relu).  L1 wavefronts/layer: 8.2K -> 4.6K.
// (Round 6 = Round 5 resubmit; removed static-guarded cudaFuncSetAttribute.)
// ---------------------------------------------------------------------------

#define B_    1024
#define T_    64
#define OB_   64
#define AC_   16
#define AUG_  32
#define H_    256
#define IN_   112   // OB + AC + AUG
#define OUT_  96    // OB + AUG
#define R_    8     // rows per CTA
#define NCTA  (B_ / R_)   // 128
#define NTHR  512

__device__ float g_W0t[IN_ * H_];     // [k<112][j<256]
__device__ float g_W1t[H_ * H_];      // [k<256][j<256]
__device__ float g_W2t[H_ * H_];
__device__ float g_W3t[H_ * 128];     // [k<256][j<128], cols 96..127 zero

__constant__ float cAT[6][5] = {
    {0.f, 0.f, 0.f, 0.f, 0.f},
    {1.0f / 5.0f, 0.f, 0.f, 0.f, 0.f},
    {3.0f / 40.0f, 9.0f / 40.0f, 0.f, 0.f, 0.f},
    {44.0f / 45.0f, -56.0f / 15.0f, 32.0f / 9.0f, 0.f, 0.f},
    {19372.0f / 6561.0f, -25360.0f / 2187.0f, 64448.0f / 6561.0f, -212.0f / 729.0f, 0.f},
    {9017.0f / 3168.0f, -355.0f / 33.0f, 46732.0f / 5247.0f, 49.0f / 176.0f, -5103.0f / 18656.0f}
};
__constant__ float cB[6] = {
    35.0f / 384.0f, 0.0f, 500.0f / 1113.0f, 125.0f / 192.0f,
    -2187.0f / 6784.0f, 11.0f / 84.0f
};

__global__ void transpose_k(const float* __restrict__ W0, const float* __restrict__ W1,
                            const float* __restrict__ W2, const float* __restrict__ W3) {
    int i = blockIdx.x * blockDim.x + threadIdx.x;   // 65536 threads
    if (i < H_ * IN_)  { int j = i / IN_, k = i % IN_;  g_W0t[k * H_ + j] = W0[i]; }
    if (i < H_ * H_)   { int j = i >> 8, k = i & 255;   g_W1t[k * H_ + j] = W1[i];
                                                        g_W2t[k * H_ + j] = W2[i]; }
    if (i < H_ * 128)  { int k = i >> 7, j = i & 127;
                         g_W3t[k * 128 + j] = (j < OUT_) ? W3[j * H_ + k] : 0.0f; }
}

struct Smem {
    float sy  [R_ * OUT_];          // 768
    float sks [6 * R_ * OUT_];      // 4608
    float sxs [R_ * IN_];           // 896
    float shA [R_ * H_];            // 2048
    float shB [R_ * H_];            // 2048
    float sacs[12 * R_ * AC_];      // 1536
    float spart[3][R_ * H_];        // 6144 (partials, groups 1..3)
    float shh [R_];
    int   sidx[12 * R_];
};

// Hidden layer (N=256), K-split x4. thread = 2 cols x 8 rows x nk4*4 k.
__device__ __forceinline__ void layer_h2(const float* __restrict__ Wt,
                                         const float* __restrict__ xin, int xs, int nk4,
                                         const float* __restrict__ bias,
                                         float* __restrict__ xout,
                                         int kg, int c2, float (*sp)[R_ * H_]) {
    const int col = c2 * 2;
    const float* wp = Wt + col;
    const int kbase = kg * nk4 * 4;
    float2 acc[R_];
#pragma unroll
    for (int r = 0; r < R_; r++) acc[r] = make_float2(0.f, 0.f);
#pragma unroll 4
    for (int k4 = 0; k4 < nk4; k4++) {
        const int k = kbase + k4 * 4;
        const float2 w0 = *(const float2*)(wp + (k + 0) * H_);
        const float2 w1 = *(const float2*)(wp + (k + 1) * H_);
        const float2 w2 = *(const float2*)(wp + (k + 2) * H_);
        const float2 w3 = *(const float2*)(wp + (k + 3) * H_);
#pragma unroll
        for (int r = 0; r < R_; r++) {
            const float4 x = *(const float4*)(xin + r * xs + k);
            acc[r].x += w0.x * x.x; acc[r].y += w0.y * x.x;
            acc[r].x += w1.x * x.y; acc[r].y += w1.y * x.y;
            acc[r].x += w2.x * x.z; acc[r].y += w2.y * x.z;
            acc[r].x += w3.x * x.w; acc[r].y += w3.y * x.w;
        }
    }
    if (kg > 0) {
#pragma unroll
        for (int r = 0; r < R_; r++)
            *(float2*)(&sp[kg - 1][r * H_ + col]) = acc[r];
    }
    __syncthreads();
    if (kg == 0) {
        const float2 b = *(const float2*)(bias + col);
#pragma unroll
        for (int r = 0; r < R_; r++) {
            const float2 p1 = *(const float2*)(&sp[0][r * H_ + col]);
            const float2 p2 = *(const float2*)(&sp[1][r * H_ + col]);
            const float2 p3 = *(const float2*)(&sp[2][r * H_ + col]);
            float vx = acc[r].x + p1.x + p2.x + p3.x + b.x;
            float vy = acc[r].y + p1.y + p2.y + p3.y + b.y;
            *(float2*)(xout + r * H_ + col) =
                make_float2(fmaxf(vx, 0.f), fmaxf(vy, 0.f));
        }
    }
    __syncthreads();
}

// Output layer (N padded to 128), K-split x4. thread = 1 col x 8 rows x 64 k.
__device__ __forceinline__ void layer_o2(const float* __restrict__ Wt,
                                         const float* __restrict__ xin,
                                         const float* __restrict__ b3,
                                         float* __restrict__ ks,
                                         int kg, int c, float (*sp)[R_ * H_]) {
    const float* wp = Wt + c;
    const int kbase = kg * 64;
    float acc[R_];
#pragma unroll
    for (int r = 0; r < R_; r++) acc[r] = 0.f;
#pragma unroll 4
    for (int k4 = 0; k4 < 16; k4++) {
        const int k = kbase + k4 * 4;
        const float w0 = wp[(k + 0) * 128];
        const float w1 = wp[(k + 1) * 128];
        const float w2 = wp[(k + 2) * 128];
        const float w3 = wp[(k + 3) * 128];
#pragma unroll
        for (int r = 0; r < R_; r++) {
            const float4 x = *(const float4*)(xin + r * H_ + k);
            acc[r] += w0 * x.x; acc[r] += w1 * x.y;
            acc[r] += w2 * x.z; acc[r] += w3 * x.w;
        }
    }
    if (kg > 0) {
#pragma unroll
        for (int r = 0; r < R_; r++)
            sp[kg - 1][r * 128 + c] = acc[r];
    }
    __syncthreads();
    if (kg == 0 && c < OUT_) {
        const float b = b3[c];
#pragma unroll
        for (int r = 0; r < R_; r++) {
            ks[r * OUT_ + c] = acc[r] + sp[0][r * 128 + c] + sp[1][r * 128 + c]
                               + sp[2][r * 128 + c] + b;
        }
    }
    __syncthreads();
}

__global__ void __launch_bounds__(NTHR, 1)
node_kernel(const float* __restrict__ ob, const float* __restrict__ acs,
            const float* __restrict__ times,
            const float* __restrict__ b0, const float* __restrict__ b1,
            const float* __restrict__ b2, const float* __restrict__ b3,
            float* __restrict__ out) {
    extern __shared__ __align__(16) char smem_raw[];
    Smem* sm = reinterpret_cast<Smem*>(smem_raw);

    const int tid  = threadIdx.x;
    const int kg   = tid >> 7;          // K-group 0..3
    const int c2   = tid & 127;         // col-pair (hidden) / col (output)
    const int row0 = blockIdx.x * R_;

    // y0 = [ob, zeros(AUG)]; emit save slot t=0
    for (int idx = tid; idx < R_ * OUT_; idx += NTHR) {
        int r = idx / OUT_, e = idx - r * OUT_;
        float v = (e < OB_) ? ob[(row0 + r) * OB_ + e] : 0.0f;
        sm->sy[idx] = v;
        if (e < OB_) out[(size_t)(row0 + r) * T_ * OB_ + e] = v;
    }
    __syncthreads();

    for (int j = 0; j < T_ - 1; j++) {
        // --- interval prologue: per-row h + 12 stage action indices ---
        if (tid < R_) {
            const int r = tid;
            const float* tsr = times + (size_t)(row0 + r) * T_;
            const float t0 = tsr[j], t1 = tsr[j + 1];
            const float h = (t1 - t0) / 2.0f;          // N_SUB = 2
            sm->shh[r] = h;
            for (int sub = 0; sub < 2; sub++) {
                const float t = t0 + (float)sub * h;
                float st[6];
                st[0] = t;
                st[1] = t + h / 5.0f;
                st[2] = t + (3.0f * h) / 10.0f;
                st[3] = t + (4.0f * h) / 5.0f;
                st[4] = t + (8.0f * h) / 9.0f;
                st[5] = t + h;
                for (int s = 0; s < 6; s++) {
                    int cnt = 0;                       // searchsorted(side='right')
                    for (int i = 0; i < T_; i++) cnt += (tsr[i] <= st[s]) ? 1 : 0;
                    int ai = cnt - 1;
                    ai = max(0, min(ai, T_ - 1));
                    sm->sidx[(sub * 6 + s) * R_ + r] = ai;
                }
            }
        }
        __syncthreads();
        // Prefetch the 12 action vectors for this interval
        for (int idx = tid; idx < 12 * R_ * AC_; idx += NTHR) {
            int s12 = idx / (R_ * AC_);
            int rem = idx - s12 * (R_ * AC_);
            int r = rem >> 4, c = rem & 15;
            sm->sacs[idx] = acs[(size_t)(row0 + r) * T_ * AC_ +
                                (size_t)sm->sidx[s12 * R_ + r] * AC_ + c];
        }
        __syncthreads();

        for (int sub = 0; sub < 2; sub++) {
            for (int s = 0; s < 6; s++) {
                // Stage input: y + h * sum_i A[s][i] * k_i   (+ action tail)
                for (int idx = tid; idx < R_ * OUT_; idx += NTHR) {
                    int r = idx / OUT_, e = idx - r * OUT_;
                    float x = sm->sy[idx];
                    if (s > 0) {
                        float acc = 0.0f;
                        for (int i = 0; i < s; i++)
                            acc += cAT[s][i] * sm->sks[(i * R_ + r) * OUT_ + e];
                        x += sm->shh[r] * acc;
                    }
                    sm->sxs[r * IN_ + e] = x;
                }
                if (tid < R_ * AC_) {
                    int r = tid >> 4;
                    sm->sxs[r * IN_ + OUT_ + (tid & 15)] =
                        sm->sacs[(sub * 6 + s) * R_ * AC_ + tid];
                }
                __syncthreads();

                layer_h2(g_W0t, sm->sxs, IN_, 7,  b0, sm->shA, kg, c2, sm->spart);
                layer_h2(g_W1t, sm->shA, H_, 16, b1, sm->shB, kg, c2, sm->spart);
                layer_h2(g_W2t, sm->shB, H_, 16, b2, sm->shA, kg, c2, sm->spart);
                layer_o2(g_W3t, sm->shA, b3,
                         sm->sks + s * R_ * OUT_, kg, c2, sm->spart);
            }
            // y += h * sum_i b_i * k_i
            for (int idx = tid; idx < R_ * OUT_; idx += NTHR) {
                int r = idx / OUT_, e = idx - r * OUT_;
                float acc = 0.0f;
                for (int i = 0; i < 6; i++)
                    acc += cB[i] * sm->sks[(i * R_ + r) * OUT_ + e];
                sm->sy[idx] += sm->shh[r] * acc;
            }
            __syncthreads();
        }
        // Save observable part at t_{j+1}
        for (int idx = tid; idx < R_ * OB_; idx += NTHR) {
            int r = idx >> 6, c = idx & 63;
            out[(size_t)(row0 + r) * T_ * OB_ + (size_t)(j + 1) * OB_ + c] =
                sm->sy[r * OUT_ + c];
        }
        __syncthreads();
    }
}

extern "C" void kernel_launch(void* const* d_in, const int* in_sizes, int n_in,
                              void* d_out, int out_size) {
    const float* ob    = (const float*)d_in[0];
    const float* acs   = (const float*)d_in[1];
    const float* times = (const float*)d_in[2];
    const float* W0    = (const float*)d_in[3];
    const float* b0    = (const float*)d_in[4];
    const float* W1    = (const float*)d_in[5];
    const float* b1    = (const float*)d_in[6];
    const float* W2    = (const float*)d_in[7];
    const float* b2    = (const float*)d_in[8];
    const float* W3    = (const float*)d_in[9];
    const float* b3    = (const float*)d_in[10];
    float* out = (float*)d_out;

    // Unconditional (no static guard): cudaFuncSetAttribute is not a stream
    // op, safe during graph capture, idempotent and deterministic.
    cudaFuncSetAttribute(node_kernel,
                         cudaFuncAttributeMaxDynamicSharedMemorySize,
                         (int)sizeof(Smem));

    transpose_k<<<256, 256>>>(W0, W1, W2, W3);
    node_kernel<<<NCTA, NTHR, sizeof(Smem)>>>(ob, acs, times, b0, b1, b2, b3, out);
}

// round 8
// speedup vs baseline: 1.7423x; 1.1482x over previous
#include <cuda_runtime.h>

// ---------------------------------------------------------------------------
// NeuralODE (Dopri5, piecewise-constant actions) — round 7: packed fp32.
// 128 CTAs x 512 threads, 8 rows/CTA, K-split x4 (weights loaded once/CTA).
// NEW: all activations/state stored ROW-PAIR INTERLEAVED [rp][k][2] so
// fma.rn.f32x2 (Blackwell packed fp32, PTX-only) computes 2 rows per
// instruction with zero x-packing cost; only w needs a pack(w,w) mov.
// Halves the FFMA issue/pipe cost that Round-6 profiling showed binding.
// Numerics identical to scalar FFMA (f32x2 = two independent rn FMAs).
// ---------------------------------------------------------------------------

#define B_    1024
#define T_    64
#define OB_   64
#define AC_   16
#define AUG_  32
#define H_    256
#define IN_   112    // OB + AC + AUG
#define INP_  128    // padded K for layer 0
#define OUT_  96     // OB + AUG
#define R_    8      // rows per CTA
#define RP_   4      // row pairs per CTA
#define NCTA  (B_ / R_)   // 128
#define NTHR  512

typedef unsigned long long u64;

#define PK2(d, lo, hi) asm("mov.b64 %0, {%1, %2};" : "=l"(d) : "f"(lo), "f"(hi))
#define UPK2(lo, hi, s) asm("mov.b64 {%0, %1}, %2;" : "=f"(lo), "=f"(hi) : "l"(s))
#define FMA2(d, a, b, c) asm("fma.rn.f32x2 %0, %1, %2, %3;" : "=l"(d) : "l"(a), "l"(b), "l"(c))
#define ADD2(d, a, b) asm("add.rn.f32x2 %0, %1, %2;" : "=l"(d) : "l"(a), "l"(b))

__device__ float g_W0t[INP_ * H_];    // [k<128][j<256], k>=112 zero
__device__ float g_W1t[H_ * H_];      // [k<256][j<256]
__device__ float g_W2t[H_ * H_];
__device__ float g_W3t[H_ * 128];     // [k<256][j<128], cols 96..127 zero

__constant__ float cAT[6][5] = {
    {0.f, 0.f, 0.f, 0.f, 0.f},
    {1.0f / 5.0f, 0.f, 0.f, 0.f, 0.f},
    {3.0f / 40.0f, 9.0f / 40.0f, 0.f, 0.f, 0.f},
    {44.0f / 45.0f, -56.0f / 15.0f, 32.0f / 9.0f, 0.f, 0.f},
    {19372.0f / 6561.0f, -25360.0f / 2187.0f, 64448.0f / 6561.0f, -212.0f / 729.0f, 0.f},
    {9017.0f / 3168.0f, -355.0f / 33.0f, 46732.0f / 5247.0f, 49.0f / 176.0f, -5103.0f / 18656.0f}
};
__constant__ float cB[6] = {
    35.0f / 384.0f, 0.0f, 500.0f / 1113.0f, 125.0f / 192.0f,
    -2187.0f / 6784.0f, 11.0f / 84.0f
};

__global__ void transpose_k(const float* __restrict__ W0, const float* __restrict__ W1,
                            const float* __restrict__ W2, const float* __restrict__ W3) {
    int i = blockIdx.x * blockDim.x + threadIdx.x;   // 65536 threads
    if (i < INP_ * H_) { int k = i >> 8, j = i & 255;
                         g_W0t[i] = (k < IN_) ? W0[j * IN_ + k] : 0.0f; }
    if (i < H_ * H_)   { int j = i >> 8, k = i & 255;   g_W1t[k * H_ + j] = W1[i];
                                                        g_W2t[k * H_ + j] = W2[i]; }
    if (i < H_ * 128)  { int k = i >> 7, j = i & 127;
                         g_W3t[k * 128 + j] = (j < OUT_) ? W3[j * H_ + k] : 0.0f; }
}

// Interleaved layouts: element (rp, e, p) at offset (rp*STRIDE + e)*2 + p,
// holding row r = rp*2 + p.
struct Smem {
    float sy  [RP_ * OUT_ * 2];          // 768
    float sks [6 * RP_ * OUT_ * 2];      // 4608
    float sxs [RP_ * INP_ * 2];          // 1024 (k in [112,128) stays zero)
    float shA [RP_ * H_ * 2];            // 2048
    float shB [RP_ * H_ * 2];            // 2048
    float sacs[12 * RP_ * AC_ * 2];      // 1536
    float spart[3][RP_ * H_ * 2];        // 6144 (K-split partials, groups 1-3)
    float shh [R_];
    int   sidx[12 * R_];
};

// Hidden layer (N=256), K-split x4, packed rows.
// thread = 2 cols x 4 row-pairs; kg owns k in [kg*KP/4, (kg+1)*KP/4).
__device__ __forceinline__ void layer_h2(const float* __restrict__ Wt,
                                         const float* __restrict__ xin, int KP,
                                         const float* __restrict__ bias,
                                         float* __restrict__ xout,
                                         int kg, int c2, float (*sp)[RP_ * H_ * 2]) {
    const int col = c2 * 2;
    const float* wp = Wt + col;
    const int nk = KP >> 2;
    const int kbase = kg * nk;
    u64 acc[2][RP_];
#pragma unroll
    for (int c = 0; c < 2; c++)
#pragma unroll
        for (int rp = 0; rp < RP_; rp++) acc[c][rp] = 0ull;
#pragma unroll 4
    for (int kk = 0; kk < nk; kk += 2) {
        const int k = kbase + kk;
        const float2 wa = *(const float2*)(wp + k * H_);
        const float2 wb = *(const float2*)(wp + (k + 1) * H_);
        u64 wa0, wa1, wb0, wb1;
        PK2(wa0, wa.x, wa.x); PK2(wa1, wa.y, wa.y);
        PK2(wb0, wb.x, wb.x); PK2(wb1, wb.y, wb.y);
#pragma unroll
        for (int rp = 0; rp < RP_; rp++) {
            const ulonglong2 xv =
                *reinterpret_cast<const ulonglong2*>(xin + (rp * KP + k) * 2);
            FMA2(acc[0][rp], wa0, xv.x, acc[0][rp]);
            FMA2(acc[1][rp], wa1, xv.x, acc[1][rp]);
            FMA2(acc[0][rp], wb0, xv.y, acc[0][rp]);
            FMA2(acc[1][rp], wb1, xv.y, acc[1][rp]);
        }
    }
    if (kg > 0) {
#pragma unroll
        for (int c = 0; c < 2; c++)
#pragma unroll
            for (int rp = 0; rp < RP_; rp++)
                *reinterpret_cast<u64*>(&sp[kg - 1][(rp * H_ + col + c) * 2]) = acc[c][rp];
    }
    __syncthreads();
    if (kg == 0) {
#pragma unroll
        for (int c = 0; c < 2; c++) {
            const float b = bias[col + c];
#pragma unroll
            for (int rp = 0; rp < RP_; rp++) {
                u64 a = acc[c][rp];
                const int off = (rp * H_ + col + c) * 2;
                u64 p0 = *reinterpret_cast<const u64*>(&sp[0][off]);
                u64 p1 = *reinterpret_cast<const u64*>(&sp[1][off]);
                u64 p2 = *reinterpret_cast<const u64*>(&sp[2][off]);
                ADD2(a, a, p0); ADD2(a, a, p1); ADD2(a, a, p2);
                float v0, v1; UPK2(v0, v1, a);
                v0 = fmaxf(v0 + b, 0.f); v1 = fmaxf(v1 + b, 0.f);
                *(float2*)(xout + off) = make_float2(v0, v1);
            }
        }
    }
    __syncthreads();
}

// Output layer (N padded 128, K=256): thread = 1 col x 4 row-pairs.
__device__ __forceinline__ void layer_o2(const float* __restrict__ Wt,
                                         const float* __restrict__ xin,
                                         const float* __restrict__ b3,
                                         float* __restrict__ ks,
                                         int kg, int c, float (*sp)[RP_ * H_ * 2]) {
    const float* wp = Wt + c;
    const int kbase = kg * 64;
    u64 acc[RP_];
#pragma unroll
    for (int rp = 0; rp < RP_; rp++) acc[rp] = 0ull;
#pragma unroll 4
    for (int kk = 0; kk < 64; kk += 2) {
        const int k = kbase + kk;
        const float w0 = wp[k * 128];
        const float w1 = wp[(k + 1) * 128];
        u64 w0p, w1p;
        PK2(w0p, w0, w0); PK2(w1p, w1, w1);
#pragma unroll
        for (int rp = 0; rp < RP_; rp++) {
            const ulonglong2 xv =
                *reinterpret_cast<const ulonglong2*>(xin + (rp * H_ + k) * 2);
            FMA2(acc[rp], w0p, xv.x, acc[rp]);
            FMA2(acc[rp], w1p, xv.y, acc[rp]);
        }
    }
    if (kg > 0) {
#pragma unroll
        for (int rp = 0; rp < RP_; rp++)
            *reinterpret_cast<u64*>(&sp[kg - 1][(rp * H_ + c) * 2]) = acc[rp];
    }
    __syncthreads();
    if (kg == 0 && c < OUT_) {
        const float b = b3[c];
#pragma unroll
        for (int rp = 0; rp < RP_; rp++) {
            u64 a = acc[rp];
            const int off = (rp * H_ + c) * 2;
            u64 p0 = *reinterpret_cast<const u64*>(&sp[0][off]);
            u64 p1 = *reinterpret_cast<const u64*>(&sp[1][off]);
            u64 p2 = *reinterpret_cast<const u64*>(&sp[2][off]);
            ADD2(a, a, p0); ADD2(a, a, p1); ADD2(a, a, p2);
            float v0, v1; UPK2(v0, v1, a);
            *(float2*)(ks + (rp * OUT_ + c) * 2) = make_float2(v0 + b, v1 + b);
        }
    }
    __syncthreads();
}

__global__ void __launch_bounds__(NTHR, 1)
node_kernel(const float* __restrict__ ob, const float* __restrict__ acs,
            const float* __restrict__ times,
            const float* __restrict__ b0, const float* __restrict__ b1,
            const float* __restrict__ b2, const float* __restrict__ b3,
            float* __restrict__ out) {
    extern __shared__ __align__(16) char smem_raw[];
    Smem* sm = reinterpret_cast<Smem*>(smem_raw);

    const int tid  = threadIdx.x;
    const int kg   = tid >> 7;          // K-group 0..3
    const int c2   = tid & 127;         // col-pair (hidden) / col (output)
    const int row0 = blockIdx.x * R_;

    // Zero the K-pad region of sxs (e in [112,128)); never written again.
    if (tid < RP_ * 16 * 2) {
        int rp = tid >> 5, rem = tid & 31;
        sm->sxs[(rp * INP_ + IN_ + (rem >> 1)) * 2 + (rem & 1)] = 0.0f;
    }
    // y0 = [ob, zeros(AUG)] interleaved; emit save slot t=0
    for (int idx = tid; idx < RP_ * OUT_ * 2; idx += NTHR) {
        int rp = idx / (OUT_ * 2), rem = idx - rp * (OUT_ * 2);
        int e = rem >> 1, p = rem & 1, r = rp * 2 + p;
        float v = (e < OB_) ? ob[(row0 + r) * OB_ + e] : 0.0f;
        sm->sy[idx] = v;
        if (e < OB_) out[(size_t)(row0 + r) * T_ * OB_ + e] = v;
    }
    __syncthreads();

    for (int j = 0; j < T_ - 1; j++) {
        // --- interval prologue: per-row h + 12 stage action indices ---
        if (tid < R_) {
            const int r = tid;
            const float* tsr = times + (size_t)(row0 + r) * T_;
            const float t0 = tsr[j], t1 = tsr[j + 1];
            const float h = (t1 - t0) / 2.0f;          // N_SUB = 2
            sm->shh[r] = h;
            for (int sub = 0; sub < 2; sub++) {
                const float t = t0 + (float)sub * h;
                float st[6];
                st[0] = t;
                st[1] = t + h / 5.0f;
                st[2] = t + (3.0f * h) / 10.0f;
                st[3] = t + (4.0f * h) / 5.0f;
                st[4] = t + (8.0f * h) / 9.0f;
                st[5] = t + h;
                for (int s = 0; s < 6; s++) {
                    int cnt = 0;                       // searchsorted(side='right')
                    for (int i = 0; i < T_; i++) cnt += (tsr[i] <= st[s]) ? 1 : 0;
                    int ai = cnt - 1;
                    ai = max(0, min(ai, T_ - 1));
                    sm->sidx[(sub * 6 + s) * R_ + r] = ai;
                }
            }
        }
        __syncthreads();
        // Prefetch 12 action vectors, interleaved [s12][rp][c][2]
        for (int idx = tid; idx < 12 * RP_ * AC_ * 2; idx += NTHR) {
            int s12 = idx >> 7;                 // /(RP_*AC_*2)=128
            int rem = idx & 127;
            int rp = rem >> 5, rem2 = rem & 31;
            int c = rem2 >> 1, p = rem2 & 1, r = rp * 2 + p;
            sm->sacs[idx] = acs[(size_t)(row0 + r) * T_ * AC_ +
                                (size_t)sm->sidx[s12 * R_ + r] * AC_ + c];
        }
        __syncthreads();

        for (int sub = 0; sub < 2; sub++) {
            for (int s = 0; s < 6; s++) {
                // Stage input (interleaved): y + h * sum_i A[s][i] * k_i
                for (int idx = tid; idx < RP_ * OUT_ * 2; idx += NTHR) {
                    int rp = idx / (OUT_ * 2), rem = idx - rp * (OUT_ * 2);
                    int e = rem >> 1, p = rem & 1, r = rp * 2 + p;
                    float x = sm->sy[idx];
                    if (s > 0) {
                        float acc = 0.0f;
                        for (int i = 0; i < s; i++)
                            acc += cAT[s][i] * sm->sks[i * (RP_ * OUT_ * 2) + idx];
                        x += sm->shh[r] * acc;
                    }
                    sm->sxs[(rp * INP_ + e) * 2 + p] = x;
                }
                if (tid < RP_ * AC_ * 2) {
                    int rp = tid >> 5, rem2 = tid & 31;
                    int c = rem2 >> 1, p = rem2 & 1;
                    sm->sxs[(rp * INP_ + OUT_ + c) * 2 + p] =
                        sm->sacs[(sub * 6 + s) * 128 + tid];
                }
                __syncthreads();

                layer_h2(g_W0t, sm->sxs, INP_, b0, sm->shA, kg, c2, sm->spart);
                layer_h2(g_W1t, sm->shA, H_,   b1, sm->shB, kg, c2, sm->spart);
                layer_h2(g_W2t, sm->shB, H_,   b2, sm->shA, kg, c2, sm->spart);
                layer_o2(g_W3t, sm->shA, b3,
                         sm->sks + s * (RP_ * OUT_ * 2), kg, c2, sm->spart);
            }
            // y += h * sum_i b_i * k_i
            for (int idx = tid; idx < RP_ * OUT_ * 2; idx += NTHR) {
                int rp = idx / (OUT_ * 2), rem = idx - rp * (OUT_ * 2);
                int p = rem & 1, r = rp * 2 + p;
                float acc = 0.0f;
                for (int i = 0; i < 6; i++)
                    acc += cB[i] * sm->sks[i * (RP_ * OUT_ * 2) + idx];
                sm->sy[idx] += sm->shh[r] * acc;
            }
            __syncthreads();
        }
        // Save observable part at t_{j+1}
        for (int idx = tid; idx < RP_ * OB_ * 2; idx += NTHR) {
            int rp = idx >> 7, rem = idx & 127;
            int c = rem >> 1, p = rem & 1, r = rp * 2 + p;
            out[(size_t)(row0 + r) * T_ * OB_ + (size_t)(j + 1) * OB_ + c] =
                sm->sy[(rp * OUT_ + c) * 2 + p];
        }
        __syncthreads();
    }
}

extern "C" void kernel_launch(void* const* d_in, const int* in_sizes, int n_in,
                              void* d_out, int out_size) {
    const float* ob    = (const float*)d_in[0];
    const float* acs   = (const float*)d_in[1];
    const float* times = (const float*)d_in[2];
    const float* W0    = (const float*)d_in[3];
    const float* b0    = (const float*)d_in[4];
    const float* W1    = (const float*)d_in[5];
    const float* b1    = (const float*)d_in[6];
    const float* W2    = (const float*)d_in[7];
    const float* b2    = (const float*)d_in[8];
    const float* W3    = (const float*)d_in[9];
    const float* b3    = (const float*)d_in[10];
    float* out = (float*)d_out;

    cudaFuncSetAttribute(node_kernel,
                         cudaFuncAttributeMaxDynamicSharedMemorySize,
                         (int)sizeof(Smem));

    transpose_k<<<256, 256>>>(W0, W1, W2, W3);
    node_kernel<<<NCTA, NTHR, sizeof(Smem)>>>(ob, acs, times, b0, b1, b2, b3, out);
}

// round 10
// speedup vs baseline: 1.7676x; 1.0145x over previous
#include <cuda_runtime.h>

// ---------------------------------------------------------------------------
// NeuralODE (Dopri5) — round 9 (= round 8 resubmit after infra failure).
// 128 CTAs x 512 threads, 8 rows/CTA (4 packed row-pairs), K-split weights
// loaded once per CTA. Hidden layers KG=4/C=2; output layer KG=8/C=2.
// Distributed reductions (all 512 threads, lane-consecutive smem patterns).
// Output-layer reduce FUSES: k_s store, next-stage input build, y-update,
// and global saves -> removes 3 elementwise phases + barriers per stage.
// All smem strides power-of-2. Numerics = fp32 (f32x2 = 2 independent FMAs).
// ---------------------------------------------------------------------------

#define B_    1024
#define T_    64
#define OB_   64
#define AC_   16
#define H_    256
#define IN_   112
#define INP_  128
#define OUT_  96
#define R_    8
#define RP_   4
#define NCTA  (B_ / R_)
#define NTHR  512

typedef unsigned long long u64;

#define PK2(d, lo, hi) asm("mov.b64 %0, {%1, %2};" : "=l"(d) : "f"(lo), "f"(hi))
#define UPK2(lo, hi, s) asm("mov.b64 {%0, %1}, %2;" : "=f"(lo), "=f"(hi) : "l"(s))
#define FMA2(d, a, b, c) asm("fma.rn.f32x2 %0, %1, %2, %3;" : "=l"(d) : "l"(a), "l"(b), "l"(c))
#define ADD2(d, a, b) asm("add.rn.f32x2 %0, %1, %2;" : "=l"(d) : "l"(a), "l"(b))

__device__ float g_W0t[INP_ * H_];    // [k<128][j<256], k>=112 zero
__device__ float g_W1t[H_ * H_];
__device__ float g_W2t[H_ * H_];
__device__ float g_W3t[H_ * 128];     // [k<256][j<128], cols 96..127 zero

__constant__ float cAT[6][5] = {
    {0.f, 0.f, 0.f, 0.f, 0.f},
    {1.0f / 5.0f, 0.f, 0.f, 0.f, 0.f},
    {3.0f / 40.0f, 9.0f / 40.0f, 0.f, 0.f, 0.f},
    {44.0f / 45.0f, -56.0f / 15.0f, 32.0f / 9.0f, 0.f, 0.f},
    {19372.0f / 6561.0f, -25360.0f / 2187.0f, 64448.0f / 6561.0f, -212.0f / 729.0f, 0.f},
    {9017.0f / 3168.0f, -355.0f / 33.0f, 46732.0f / 5247.0f, 49.0f / 176.0f, -5103.0f / 18656.0f}
};
__constant__ float cB[6] = {
    35.0f / 384.0f, 0.0f, 500.0f / 1113.0f, 125.0f / 192.0f,
    -2187.0f / 6784.0f, 11.0f / 84.0f
};

__global__ void transpose_k(const float* __restrict__ W0, const float* __restrict__ W1,
                            const float* __restrict__ W2, const float* __restrict__ W3) {
    int i = blockIdx.x * blockDim.x + threadIdx.x;
    if (i < INP_ * H_) { int k = i >> 8, j = i & 255;
                         g_W0t[i] = (k < IN_) ? W0[j * IN_ + k] : 0.0f; }
    if (i < H_ * H_)   { int j = i >> 8, k = i & 255;   g_W1t[k * H_ + j] = W1[i];
                                                        g_W2t[k * H_ + j] = W2[i]; }
    if (i < H_ * 128)  { int k = i >> 7, j = i & 127;
                         g_W3t[k * 128 + j] = (j < OUT_) ? W3[j * H_ + k] : 0.0f; }
}

struct __align__(16) Smem {
    u64   spart[4096];            // 32KB: layer_h 4x1024 / layer_o 8x512
    float shA [RP_ * H_ * 2];     // 8KB, rp-stride 256, packed pairs
    float shB [RP_ * H_ * 2];     // 8KB
    float sxs [RP_ * 128 * 2];    // 4KB: e<96 state, 96..111 action, rest 0
    float sy  [RP_ * 128 * 2];    // 4KB
    float sks [6 * RP_ * 128 * 2];// 24KB
    float sacs[12 * RP_ * AC_ * 2];// 6KB: [s12][rp][ac][2]
    u64   shh2[RP_];
    float shh [R_];
    int   sidx[12 * R_];
    float sb0[256], sb1[256], sb2[256], sb3[96];
};

// Hidden layer (N=256): KG=4, C=2. thread: kg = tid>>7, cg = tid&127.
__device__ __forceinline__ void layer_h(const float* __restrict__ Wt,
                                        const float* __restrict__ xin, int KP,
                                        const float* __restrict__ sb,
                                        float* __restrict__ xout,
                                        int kg, int cg, u64* __restrict__ sp) {
    const int col0 = cg * 2;
    const float* wp = Wt + col0;
    const int nk = KP >> 2;
    const int kbase = kg * nk;
    u64 acc[2][RP_];
#pragma unroll
    for (int c = 0; c < 2; c++)
#pragma unroll
        for (int rp = 0; rp < RP_; rp++) acc[c][rp] = 0ull;
#pragma unroll 4
    for (int kk = 0; kk < nk; kk += 2) {
        const int k = kbase + kk;
        const float2 wa = *(const float2*)(wp + k * H_);
        const float2 wb = *(const float2*)(wp + (k + 1) * H_);
        u64 wa0, wa1, wb0, wb1;
        PK2(wa0, wa.x, wa.x); PK2(wa1, wa.y, wa.y);
        PK2(wb0, wb.x, wb.x); PK2(wb1, wb.y, wb.y);
#pragma unroll
        for (int rp = 0; rp < RP_; rp++) {
            const ulonglong2 xv =
                *reinterpret_cast<const ulonglong2*>(xin + (rp * KP + k) * 2);
            FMA2(acc[0][rp], wa0, xv.x, acc[0][rp]);
            FMA2(acc[1][rp], wa1, xv.x, acc[1][rp]);
            FMA2(acc[0][rp], wb0, xv.y, acc[0][rp]);
            FMA2(acc[1][rp], wb1, xv.y, acc[1][rp]);
        }
    }
    // Spill: sp[kg][c*4+rp][cg] — lane-consecutive cg
#pragma unroll
    for (int c = 0; c < 2; c++)
#pragma unroll
        for (int rp = 0; rp < RP_; rp++)
            sp[kg * 1024 + (c * 4 + rp) * 128 + cg] = acc[c][rp];
    __syncthreads();
    // Distributed reduce: 1024 u64 outputs over 512 threads (2 each)
    const int t = threadIdx.x;
#pragma unroll
    for (int oi = 0; oi < 2; oi++) {
        const int o = t + oi * 512;
        u64 v = sp[o];
        ADD2(v, v, sp[o + 1024]);
        ADD2(v, v, sp[o + 2048]);
        ADD2(v, v, sp[o + 3072]);
        const int cr = o >> 7, cgo = o & 127;
        const int c = cr >> 2, rp = cr & 3;
        const int col = cgo * 2 + c;
        const float b = sb[col];
        float v0, v1; UPK2(v0, v1, v);
        v0 = fmaxf(v0 + b, 0.f); v1 = fmaxf(v1 + b, 0.f);
        *(float2*)(xout + (rp * H_ + col) * 2) = make_float2(v0, v1);
    }
    __syncthreads();
}

// Output layer (N pad 128): KG=8, C=2. kg8 = tid>>6, cg = tid&63.
// Reduce is FUSED with the Dopri5 stage algebra.
__device__ __forceinline__ void layer_o_fused(
    const float* __restrict__ Wt, const float* __restrict__ xin,
    Smem* sm, int s, int sub, int j, int row0, float* __restrict__ out) {
    const int tid = threadIdx.x;
    const int kg = tid >> 6, cg = tid & 63;
    const int col0 = cg * 2;
    const float* wp = Wt + col0;
    const int kbase = kg * 32;
    u64* const sp = sm->spart;
    u64 acc[2][RP_];
#pragma unroll
    for (int c = 0; c < 2; c++)
#pragma unroll
        for (int rp = 0; rp < RP_; rp++) acc[c][rp] = 0ull;
#pragma unroll 4
    for (int kk = 0; kk < 32; kk += 2) {
        const int k = kbase + kk;
        const float2 wa = *(const float2*)(wp + k * 128);
        const float2 wb = *(const float2*)(wp + (k + 1) * 128);
        u64 wa0, wa1, wb0, wb1;
        PK2(wa0, wa.x, wa.x); PK2(wa1, wa.y, wa.y);
        PK2(wb0, wb.x, wb.x); PK2(wb1, wb.y, wb.y);
#pragma unroll
        for (int rp = 0; rp < RP_; rp++) {
            const ulonglong2 xv =
                *reinterpret_cast<const ulonglong2*>(xin + (rp * H_ + k) * 2);
            FMA2(acc[0][rp], wa0, xv.x, acc[0][rp]);
            FMA2(acc[1][rp], wa1, xv.x, acc[1][rp]);
            FMA2(acc[0][rp], wb0, xv.y, acc[0][rp]);
            FMA2(acc[1][rp], wb1, xv.y, acc[1][rp]);
        }
    }
#pragma unroll
    for (int c = 0; c < 2; c++)
#pragma unroll
        for (int rp = 0; rp < RP_; rp++)
            sp[kg * 512 + (c * 4 + rp) * 64 + cg] = acc[c][rp];
    __syncthreads();

    // One output per thread: o = tid -> (c, rp, cgo)
    const int o = tid;
    u64 v = sp[o];
#pragma unroll
    for (int g = 1; g < 8; g++) ADD2(v, v, sp[g * 512 + o]);
    const int cr = o >> 6, cgo = o & 63;
    const int c = cr >> 2, rp = cr & 3;
    const int col = cgo * 2 + c;
    u64* const sks64 = (u64*)sm->sks;
    u64* const sy64  = (u64*)sm->sy;
    u64* const sxs64 = (u64*)sm->sxs;
    const u64* const sacs64 = (const u64*)sm->sacs;

    if (col < OUT_) {
        const int o2 = rp * 128 + col;
        u64 bp; { const float b = sm->sb3[col]; PK2(bp, b, b); }
        u64 kn; ADD2(kn, v, bp);
        sks64[s * 512 + o2] = kn;
        const u64 y  = sy64[o2];
        const u64 hh = sm->shh2[rp];
        const u64 z = 0ull;
        if (s < 5) {
            u64 sum, ap;
            { const float a = cAT[s + 1][s]; PK2(ap, a, a); }
            FMA2(sum, ap, kn, z);
            for (int i = 0; i < s; i++) {
                const float a = cAT[s + 1][i]; PK2(ap, a, a);
                FMA2(sum, ap, sks64[i * 512 + o2], sum);
            }
            u64 x; FMA2(x, hh, sum, y);
            sxs64[o2] = x;
        } else {
            u64 sum, ap;
            { const float a = cB[5]; PK2(ap, a, a); }
            FMA2(sum, ap, kn, z);
            { const float a = cB[4]; PK2(ap, a, a); FMA2(sum, ap, sks64[4 * 512 + o2], sum); }
            { const float a = cB[3]; PK2(ap, a, a); FMA2(sum, ap, sks64[3 * 512 + o2], sum); }
            { const float a = cB[2]; PK2(ap, a, a); FMA2(sum, ap, sks64[2 * 512 + o2], sum); }
            { const float a = cB[0]; PK2(ap, a, a); FMA2(sum, ap, sks64[0 * 512 + o2], sum); }
            u64 yn; FMA2(yn, hh, sum, y);
            sy64[o2]  = yn;
            sxs64[o2] = yn;                       // state part of next stage-0 input
            if (sub == 1 && col < OB_) {
                float y0, y1; UPK2(y0, y1, yn);
                const size_t base = (size_t)(row0 + rp * 2) * T_ * OB_ +
                                    (size_t)(j + 1) * OB_ + col;
                out[base] = y0;
                out[base + (size_t)T_ * OB_] = y1;
            }
        }
    } else if (col < IN_) {                       // action tail for next stage
        const int s12n = (s < 5) ? (sub * 6 + s + 1) : ((sub == 0) ? 6 : -1);
        if (s12n >= 0)
            sxs64[rp * 128 + col] = sacs64[s12n * 64 + rp * 16 + (col - OUT_)];
    }
    __syncthreads();
}

__global__ void __launch_bounds__(NTHR, 1)
node_kernel(const float* __restrict__ ob, const float* __restrict__ acs,
            const float* __restrict__ times,
            const float* __restrict__ b0, const float* __restrict__ b1,
            const float* __restrict__ b2, const float* __restrict__ b3,
            float* __restrict__ out) {
    extern __shared__ __align__(16) char smem_raw[];
    Smem* sm = reinterpret_cast<Smem*>(smem_raw);

    const int tid  = threadIdx.x;
    const int kg4  = tid >> 7;          // hidden-layer K-group
    const int cg4  = tid & 127;         // hidden-layer col-pair
    const int row0 = blockIdx.x * R_;

    // Cache biases in smem
    if (tid < 256) { sm->sb0[tid] = b0[tid]; sm->sb1[tid] = b1[tid]; sm->sb2[tid] = b2[tid]; }
    if (tid < OUT_) sm->sb3[tid] = b3[tid];

    // Init sy (padded, packed) + emit t=0; zero sxs pad region
    {
        const int o = tid;              // o < 512 = rp*128 + col
        const int col = o & 127, rp = o >> 7;
        const int r0 = row0 + rp * 2;
        float v0 = 0.f, v1 = 0.f;
        if (col < OB_) {
            v0 = ob[r0 * OB_ + col];
            v1 = ob[(r0 + 1) * OB_ + col];
            out[(size_t)r0 * T_ * OB_ + col] = v0;
            out[(size_t)(r0 + 1) * T_ * OB_ + col] = v1;
        }
        u64 p; PK2(p, v0, v1);
        ((u64*)sm->sy)[o] = p;
        if (col >= IN_) ((u64*)sm->sxs)[o] = 0ull;   // K-pad stays zero forever
    }
    __syncthreads();

    for (int j = 0; j < T_ - 1; j++) {
        // --- interval prologue ---
        if (tid < R_) {
            const int r = tid;
            const float* tsr = times + (size_t)(row0 + r) * T_;
            const float t0 = tsr[j], t1 = tsr[j + 1];
            const float h = (t1 - t0) / 2.0f;
            sm->shh[r] = h;
            for (int sub = 0; sub < 2; sub++) {
                const float t = t0 + (float)sub * h;
                float st[6];
                st[0] = t;
                st[1] = t + h / 5.0f;
                st[2] = t + (3.0f * h) / 10.0f;
                st[3] = t + (4.0f * h) / 5.0f;
                st[4] = t + (8.0f * h) / 9.0f;
                st[5] = t + h;
                for (int s = 0; s < 6; s++) {
                    int cnt = 0;
                    for (int i = 0; i < T_; i++) cnt += (tsr[i] <= st[s]) ? 1 : 0;
                    int ai = cnt - 1;
                    ai = max(0, min(ai, T_ - 1));
                    sm->sidx[(sub * 6 + s) * R_ + r] = ai;
                }
            }
        }
        __syncthreads();
        if (tid < RP_) {
            u64 p; PK2(p, sm->shh[tid * 2], sm->shh[tid * 2 + 1]);
            sm->shh2[tid] = p;
        }
        // Prefetch 12 action vectors: sacs[s12][rp][ac][2]
        for (int idx = tid; idx < 12 * RP_ * AC_ * 2; idx += NTHR) {
            const int s12 = idx >> 7;
            const int rem = idx & 127;
            const int rp = rem >> 5, rem2 = rem & 31;
            const int c = rem2 >> 1, p = rem2 & 1, r = rp * 2 + p;
            sm->sacs[idx] = acs[(size_t)(row0 + r) * T_ * AC_ +
                                (size_t)sm->sidx[s12 * R_ + r] * AC_ + c];
        }
        __syncthreads();
        // Stage-0 input for sub=0: state copy + action tail
        {
            const int o = tid, col = o & 127, rp = o >> 7;
            if (col < OUT_)
                ((u64*)sm->sxs)[o] = ((u64*)sm->sy)[o];
            else if (col < IN_)
                ((u64*)sm->sxs)[o] =
                    ((const u64*)sm->sacs)[rp * 16 + (col - OUT_)];  // s12 = 0
        }
        __syncthreads();

        for (int sub = 0; sub < 2; sub++) {
            for (int s = 0; s < 6; s++) {
                layer_h(g_W0t, sm->sxs, 128, sm->sb0, sm->shA, kg4, cg4, sm->spart);
                layer_h(g_W1t, sm->shA, 256, sm->sb1, sm->shB, kg4, cg4, sm->spart);
                layer_h(g_W2t, sm->shB, 256, sm->sb2, sm->shA, kg4, cg4, sm->spart);
                layer_o_fused(g_W3t, sm->shA, sm, s, sub, j, row0, out);
            }
        }
    }
}

extern "C" void kernel_launch(void* const* d_in, const int* in_sizes, int n_in,
                              void* d_out, int out_size) {
    const float* ob    = (const float*)d_in[0];
    const float* acs   = (const float*)d_in[1];
    const float* times = (const float*)d_in[2];
    const float* W0    = (const float*)d_in[3];
    const float* b0    = (const float*)d_in[4];
    const float* W1    = (const float*)d_in[5];
    const float* b1    = (const float*)d_in[6];
    const float* W2    = (const float*)d_in[7];
    const float* b2    = (const float*)d_in[8];
    const float* W3    = (const float*)d_in[9];
    const float* b3    = (const float*)d_in[10];
    float* out = (float*)d_out;

    cudaFuncSetAttribute(node_kernel,
                         cudaFuncAttributeMaxDynamicSharedMemorySize,
                         (int)sizeof(Smem));

    transpose_k<<<256, 256>>>(W0, W1, W2, W3);
    node_kernel<<<NCTA, NTHR, sizeof(Smem)>>>(ob, acs, times, b0, b1, b2, b3, out);
}

// round 13
// speedup vs baseline: 1.7995x; 1.0181x over previous
#include <cuda_runtime.h>

// ---------------------------------------------------------------------------
// NeuralODE (Dopri5) — round 12 (= round 10 x-dedup resubmit, audited).
// 128 CTAs x 512 threads, 8 rows/CTA (4 packed row-pairs).
// Thread tile: KG=4 x CG=64 x RPH=2; hidden C=4, output C=2.
//   -> per-thread x traffic halves (x-wf 2048 -> 1024 per hidden layer),
//      weight wf unchanged (bytes-invariant), spill unchanged (KG=4).
// x arrays padded to stride 260 u64 so the two rp-planes per LDS hit
// different banks (1 wavefront). Fused Dopri5 epilogue.
// times cached in smem; searchsorted parallelized over 96 threads.
// Numerics = fp32 (f32x2 = 2 independent rn FMAs).
// ---------------------------------------------------------------------------

#define B_    1024
#define T_    64
#define OB_   64
#define AC_   16
#define H_    256
#define IN_   112
#define OUT_  96
#define R_    8
#define RP_   4
#define NCTA  (B_ / R_)
#define NTHR  512
#define XS    260           // u64 stride of packed x arrays (bank skew)

typedef unsigned long long u64;

#define PK2(d, lo, hi) asm("mov.b64 %0, {%1, %2};" : "=l"(d) : "f"(lo), "f"(hi))
#define UPK2(lo, hi, s) asm("mov.b64 {%0, %1}, %2;" : "=f"(lo), "=f"(hi) : "l"(s))
#define FMA2(d, a, b, c) asm("fma.rn.f32x2 %0, %1, %2, %3;" : "=l"(d) : "l"(a), "l"(b), "l"(c))
#define ADD2(d, a, b) asm("add.rn.f32x2 %0, %1, %2;" : "=l"(d) : "l"(a), "l"(b))

__device__ float g_W0t[128 * H_];     // [k<128][j<256], k>=112 zero
__device__ float g_W1t[H_ * H_];
__device__ float g_W2t[H_ * H_];
__device__ float g_W3t[H_ * 128];     // [k<256][j<128], cols 96..127 zero

__constant__ float cAT[6][5] = {
    {0.f, 0.f, 0.f, 0.f, 0.f},
    {1.0f / 5.0f, 0.f, 0.f, 0.f, 0.f},
    {3.0f / 40.0f, 9.0f / 40.0f, 0.f, 0.f, 0.f},
    {44.0f / 45.0f, -56.0f / 15.0f, 32.0f / 9.0f, 0.f, 0.f},
    {19372.0f / 6561.0f, -25360.0f / 2187.0f, 64448.0f / 6561.0f, -212.0f / 729.0f, 0.f},
    {9017.0f / 3168.0f, -355.0f / 33.0f, 46732.0f / 5247.0f, 49.0f / 176.0f, -5103.0f / 18656.0f}
};
__constant__ float cB[6] = {
    35.0f / 384.0f, 0.0f, 500.0f / 1113.0f, 125.0f / 192.0f,
    -2187.0f / 6784.0f, 11.0f / 84.0f
};

__global__ void transpose_k(const float* __restrict__ W0, const float* __restrict__ W1,
                            const float* __restrict__ W2, const float* __restrict__ W3) {
    int i = blockIdx.x * blockDim.x + threadIdx.x;
    if (i < 128 * H_)  { int k = i >> 8, j = i & 255;
                         g_W0t[i] = (k < IN_) ? W0[j * IN_ + k] : 0.0f; }
    if (i < H_ * H_)   { int j = i >> 8, k = i & 255;   g_W1t[k * H_ + j] = W1[i];
                                                        g_W2t[k * H_ + j] = W2[i]; }
    if (i < H_ * 128)  { int k = i >> 7, j = i & 127;
                         g_W3t[k * 128 + j] = (j < OUT_) ? W3[j * H_ + k] : 0.0f; }
}

struct __align__(16) Smem {
    u64   spart[4096];        // 32KB spill (hidden 4x1024 / output 4x512)
    u64   shA [RP_ * XS];     // x arrays, [rp][k] packed pairs, stride 260
    u64   shB [RP_ * XS];
    u64   sxs [RP_ * XS];
    u64   sy  [512];          // [rp][col<128]
    u64   sks [6 * 512];
    u64   sacs[12 * 64];      // [s12][rp][ac]
    u64   shh2[RP_];
    float shh [R_];
    float stimes[R_ * T_];    // 2KB, loaded once
    int   sidx[12 * R_];
    float sb0[256], sb1[256], sb2[256], sb3[96];
};

// Hidden layer (N=256): KG=4 x CG=64(C=4) x RPH=2.
__device__ __forceinline__ void layer_h(const float* __restrict__ Wt,
                                        const u64* __restrict__ xin, int nk,
                                        const float* __restrict__ sb,
                                        u64* __restrict__ xout,
                                        int kg, int lane128, u64* __restrict__ sp) {
    const int cg = lane128 >> 1, rph = lane128 & 1;
    const int col0 = cg * 4;
    const float* wp = Wt + col0;
    const int kbase = kg * nk;
    const u64* xp0 = xin + (rph * 2)     * XS + kbase;
    const u64* xp1 = xin + (rph * 2 + 1) * XS + kbase;
    u64 a00 = 0, a01 = 0, a10 = 0, a11 = 0, a20 = 0, a21 = 0, a30 = 0, a31 = 0;
#pragma unroll 4
    for (int kk = 0; kk < nk; kk += 2) {
        const float4 wA = *(const float4*)(wp + (kbase + kk) * H_);
        const float4 wB = *(const float4*)(wp + (kbase + kk + 1) * H_);
        u64 wA0, wA1, wA2, wA3, wB0, wB1, wB2, wB3;
        PK2(wA0, wA.x, wA.x); PK2(wA1, wA.y, wA.y);
        PK2(wA2, wA.z, wA.z); PK2(wA3, wA.w, wA.w);
        PK2(wB0, wB.x, wB.x); PK2(wB1, wB.y, wB.y);
        PK2(wB2, wB.z, wB.z); PK2(wB3, wB.w, wB.w);
        const ulonglong2 x0 = *(const ulonglong2*)(xp0 + kk);
        const ulonglong2 x1 = *(const ulonglong2*)(xp1 + kk);
        FMA2(a00, wA0, x0.x, a00); FMA2(a00, wB0, x0.y, a00);
        FMA2(a01, wA0, x1.x, a01); FMA2(a01, wB0, x1.y, a01);
        FMA2(a10, wA1, x0.x, a10); FMA2(a10, wB1, x0.y, a10);
        FMA2(a11, wA1, x1.x, a11); FMA2(a11, wB1, x1.y, a11);
        FMA2(a20, wA2, x0.x, a20); FMA2(a20, wB2, x0.y, a20);
        FMA2(a21, wA2, x1.x, a21); FMA2(a21, wB2, x1.y, a21);
        FMA2(a30, wA3, x0.x, a30); FMA2(a30, wB3, x0.y, a30);
        FMA2(a31, wA3, x1.x, a31); FMA2(a31, wB3, x1.y, a31);
    }
    // Spill rows (c*2+i), lane-consecutive.
    u64* spk = sp + kg * 1024 + lane128;
    spk[0 * 128] = a00; spk[1 * 128] = a01;
    spk[2 * 128] = a10; spk[3 * 128] = a11;
    spk[4 * 128] = a20; spk[5 * 128] = a21;
    spk[6 * 128] = a30; spk[7 * 128] = a31;
    __syncthreads();
    const int t = threadIdx.x;
#pragma unroll
    for (int oi = 0; oi < 2; oi++) {
        const int o = t + oi * 512;
        u64 v = sp[o];
        ADD2(v, v, sp[o + 1024]);
        ADD2(v, v, sp[o + 2048]);
        ADD2(v, v, sp[o + 3072]);
        const int c2i = o >> 7, l = o & 127;
        const int c = c2i >> 1, i = c2i & 1;
        const int col = (l >> 1) * 4 + c, rp = (l & 1) * 2 + i;
        const float b = sb[col];
        float v0, v1; UPK2(v0, v1, v);
        v0 = fmaxf(v0 + b, 0.f); v1 = fmaxf(v1 + b, 0.f);
        ((float2*)xout)[rp * XS + col] = make_float2(v0, v1);
    }
    __syncthreads();
}

// Output layer (N pad 128): KG=4 x CG=64(C=2) x RPH=2, fused Dopri5 epilogue.
__device__ __forceinline__ void layer_o_fused(
    const float* __restrict__ Wt, const u64* __restrict__ xin,
    Smem* sm, int s, int sub, int j, int row0, float* __restrict__ out) {
    const int tid = threadIdx.x;
    const int kg = tid >> 7, lane128 = tid & 127;
    const int cg = lane128 >> 1, rph = lane128 & 1;
    const int col0 = cg * 2;
    const float* wp = Wt + col0;
    const int kbase = kg * 64;
    const u64* xp0 = xin + (rph * 2)     * XS + kbase;
    const u64* xp1 = xin + (rph * 2 + 1) * XS + kbase;
    u64* const sp = sm->spart;
    u64 a00 = 0, a01 = 0, a10 = 0, a11 = 0;
#pragma unroll 4
    for (int kk = 0; kk < 64; kk += 2) {
        const float2 wA = *(const float2*)(wp + (kbase + kk) * 128);
        const float2 wB = *(const float2*)(wp + (kbase + kk + 1) * 128);
        u64 wA0, wA1, wB0, wB1;
        PK2(wA0, wA.x, wA.x); PK2(wA1, wA.y, wA.y);
        PK2(wB0, wB.x, wB.x); PK2(wB1, wB.y, wB.y);
        const ulonglong2 x0 = *(const ulonglong2*)(xp0 + kk);
        const ulonglong2 x1 = *(const ulonglong2*)(xp1 + kk);
        FMA2(a00, wA0, x0.x, a00); FMA2(a00, wB0, x0.y, a00);
        FMA2(a01, wA0, x1.x, a01); FMA2(a01, wB0, x1.y, a01);
        FMA2(a10, wA1, x0.x, a10); FMA2(a10, wB1, x0.y, a10);
        FMA2(a11, wA1, x1.x, a11); FMA2(a11, wB1, x1.y, a11);
    }
    u64* spk = sp + kg * 512 + lane128;
    spk[0 * 128] = a00; spk[1 * 128] = a01;
    spk[2 * 128] = a10; spk[3 * 128] = a11;
    __syncthreads();

    const int o = tid;
    u64 v = sp[o];
    ADD2(v, v, sp[o + 512]);
    ADD2(v, v, sp[o + 1024]);
    ADD2(v, v, sp[o + 1536]);
    const int c2i = o >> 7, l = o & 127;
    const int c = c2i >> 1, i = c2i & 1;
    const int col = (l >> 1) * 2 + c, rp = (l & 1) * 2 + i;
    u64* const sks64 = sm->sks;
    u64* const sy64  = sm->sy;
    u64* const sxs64 = sm->sxs;
    const u64* const sacs64 = sm->sacs;

    if (col < OUT_) {
        const int o2 = rp * 128 + col;
        u64 bp; { const float b = sm->sb3[col]; PK2(bp, b, b); }
        u64 kn; ADD2(kn, v, bp);
        sks64[s * 512 + o2] = kn;
        const u64 y  = sy64[o2];
        const u64 hh = sm->shh2[rp];
        const u64 z = 0ull;
        if (s < 5) {
            u64 sum, ap;
            { const float a = cAT[s + 1][s]; PK2(ap, a, a); }
            FMA2(sum, ap, kn, z);
            for (int i2 = 0; i2 < s; i2++) {
                const float a = cAT[s + 1][i2]; PK2(ap, a, a);
                FMA2(sum, ap, sks64[i2 * 512 + o2], sum);
            }
            u64 x; FMA2(x, hh, sum, y);
            sxs64[rp * XS + col] = x;
        } else {
            u64 sum, ap;
            { const float a = cB[5]; PK2(ap, a, a); }
            FMA2(sum, ap, kn, z);
            { const float a = cB[4]; PK2(ap, a, a); FMA2(sum, ap, sks64[4 * 512 + o2], sum); }
            { const float a = cB[3]; PK2(ap, a, a); FMA2(sum, ap, sks64[3 * 512 + o2], sum); }
            { const float a = cB[2]; PK2(ap, a, a); FMA2(sum, ap, sks64[2 * 512 + o2], sum); }
            { const float a = cB[0]; PK2(ap, a, a); FMA2(sum, ap, sks64[0 * 512 + o2], sum); }
            u64 yn; FMA2(yn, hh, sum, y);
            sy64[o2] = yn;
            sxs64[rp * XS + col] = yn;            // state part of next stage-0 input
            if (sub == 1 && col < OB_) {
                float y0, y1; UPK2(y0, y1, yn);
                const size_t base = (size_t)(row0 + rp * 2) * T_ * OB_ +
                                    (size_t)(j + 1) * OB_ + col;
                out[base] = y0;
                out[base + (size_t)T_ * OB_] = y1;
            }
        }
    } else if (col < IN_) {                       // action tail for next stage
        const int s12n = (s < 5) ? (sub * 6 + s + 1) : ((sub == 0) ? 6 : -1);
        if (s12n >= 0)
            sxs64[rp * XS + col] = sacs64[s12n * 64 + rp * 16 + (col - OUT_)];
    }
    __syncthreads();
}

__global__ void __launch_bounds__(NTHR, 1)
node_kernel(const float* __restrict__ ob, const float* __restrict__ acs,
            const float* __restrict__ times,
            const float* __restrict__ b0, const float* __restrict__ b1,
            const float* __restrict__ b2, const float* __restrict__ b3,
            float* __restrict__ out) {
    extern __shared__ __align__(16) char smem_raw[];
    Smem* sm = reinterpret_cast<Smem*>(smem_raw);

    const int tid  = threadIdx.x;
    const int kg   = tid >> 7;
    const int l128 = tid & 127;
    const int row0 = blockIdx.x * R_;

    // Biases + times to smem (times loaded once — constant across intervals)
    if (tid < 256) { sm->sb0[tid] = b0[tid]; sm->sb1[tid] = b1[tid]; sm->sb2[tid] = b2[tid]; }
    if (tid < OUT_) sm->sb3[tid] = b3[tid];
    sm->stimes[tid] = times[(size_t)(row0 + (tid >> 6)) * T_ + (tid & 63)];

    // Init sy (packed pairs) + emit t=0; zero sxs K-pad (col in [112,128))
    {
        const int col = tid & 127, rp = tid >> 7;
        const int r0 = row0 + rp * 2;
        float v0 = 0.f, v1 = 0.f;
        if (col < OB_) {
            v0 = ob[r0 * OB_ + col];
            v1 = ob[(r0 + 1) * OB_ + col];
            out[(size_t)r0 * T_ * OB_ + col] = v0;
            out[(size_t)(r0 + 1) * T_ * OB_ + col] = v1;
        }
        u64 p; PK2(p, v0, v1);
        sm->sy[tid] = p;
        if (col >= IN_) sm->sxs[rp * XS + col] = 0ull;
    }
    __syncthreads();

    for (int j = 0; j < T_ - 1; j++) {
        // --- interval prologue: parallel searchsorted over 96 threads ---
        if (tid < 96) {
            const int s12 = tid >> 3, r = tid & 7;
            const float* tsr = &sm->stimes[r * 64];
            const float t0 = tsr[j], t1 = tsr[j + 1];
            const float h = (t1 - t0) / 2.0f;
            if (s12 == 0) sm->shh[r] = h;
            const int sub = (s12 >= 6) ? 1 : 0;
            const int s = s12 - sub * 6;
            const float t = t0 + (float)sub * h;
            float st;
            if      (s == 0) st = t;
            else if (s == 1) st = t + h / 5.0f;
            else if (s == 2) st = t + (3.0f * h) / 10.0f;
            else if (s == 3) st = t + (4.0f * h) / 5.0f;
            else if (s == 4) st = t + (8.0f * h) / 9.0f;
            else             st = t + h;
            int cnt = 0;
            for (int i = 0; i < T_; i++) cnt += (tsr[i] <= st) ? 1 : 0;
            int ai = cnt - 1;
            ai = max(0, min(ai, T_ - 1));
            sm->sidx[s12 * R_ + r] = ai;
        }
        __syncthreads();
        if (tid < RP_) {
            u64 p; PK2(p, sm->shh[tid * 2], sm->shh[tid * 2 + 1]);
            sm->shh2[tid] = p;
        }
        // Prefetch 12 action vectors: sacs[s12][rp][ac] packed pairs
        for (int idx = tid; idx < 12 * RP_ * AC_ * 2; idx += NTHR) {
            const int s12 = idx >> 7;
            const int rem = idx & 127;
            const int rp = rem >> 5, rem2 = rem & 31;
            const int c = rem2 >> 1, p = rem2 & 1, r = rp * 2 + p;
            ((float*)sm->sacs)[s12 * 128 + rp * 32 + c * 2 + p] =
                acs[(size_t)(row0 + r) * T_ * AC_ +
                    (size_t)sm->sidx[s12 * R_ + r] * AC_ + c];
        }
        __syncthreads();
        // Stage-0 input for sub=0: state + action tail
        {
            const int col = tid & 127, rp = tid >> 7;
            if (col < OUT_)
                sm->sxs[rp * XS + col] = sm->sy[tid];
            else if (col < IN_)
                sm->sxs[rp * XS + col] = sm->sacs[rp * 16 + (col - OUT_)]; // s12=0
        }
        __syncthreads();

        for (int sub = 0; sub < 2; sub++) {
            for (int s = 0; s < 6; s++) {
                layer_h(g_W0t, sm->sxs, 32, sm->sb0, sm->shA, kg, l128, sm->spart);
                layer_h(g_W1t, sm->shA, 64, sm->sb1, sm->shB, kg, l128, sm->spart);
                layer_h(g_W2t, sm->shB, 64, sm->sb2, sm->shA, kg, l128, sm->spart);
                layer_o_fused(g_W3t, sm->shA, sm, s, sub, j, row0, out);
            }
        }
    }
}

extern "C" void kernel_launch(void* const* d_in, const int* in_sizes, int n_in,
                              void* d_out, int out_size) {
    const float* ob    = (const float*)d_in[0];
    const float* acs   = (const float*)d_in[1];
    const float* times = (const float*)d_in[2];
    const float* W0    = (const float*)d_in[3];
    const float* b0    = (const float*)d_in[4];
    const float* W1    = (const float*)d_in[5];
    const float* b1    = (const float*)d_in[6];
    const float* W2    = (const float*)d_in[7];
    const float* b2    = (const float*)d_in[8];
    const float* W3    = (const float*)d_in[9];
    const float* b3    = (const float*)d_in[10];
    float* out = (float*)d_out;

    cudaFuncSetAttribute(node_kernel,
                         cudaFuncAttributeMaxDynamicSharedMemorySize,
                         (int)sizeof(Smem));

    transpose_k<<<256, 256>>>(W0, W1, W2, W3);
    node_kernel<<<NCTA, NTHR, sizeof(Smem)>>>(ob, acs, times, b0, b1, b2, b3, out);
}

// round 14
// speedup vs baseline: 2.0703x; 1.1505x over previous
#include <cuda_runtime.h>
#include <cstdint>

// ---------------------------------------------------------------------------
// NeuralODE (Dopri5) — round 13: TMA-streamed weights.
// 128 CTAs x 512 threads, 8 rows/CTA (4 packed row-pairs).
// Weights stream L2 -> smem via cp.async.bulk (UBLKCP) into 2x64KB buffers,
// prefetch distance 2, mbarrier expect_tx/parity. Weight reads become LDS
// (no L1 fill traffic, no L2 latency exposure) — attacks the L1 pipe that
// round-12 profiling showed saturated by the LDG weight stream.
// Compute layout unchanged from round 12 (KG=4 x CG=64 x RPH=2, packed
// fp32 FMA2, fused Dopri5 epilogue) -> bit-identical numerics.
// ---------------------------------------------------------------------------

#define B_    1024
#define T_    64
#define OB_   64
#define AC_   16
#define H_    256
#define IN_   112
#define OUT_  96
#define R_    8
#define RP_   4
#define NCTA  (B_ / R_)
#define NTHR  512
#define XS    260
#define NEVAL (63 * 12)             // 756 evals
#define NCHTOT (NEVAL * 12)         // 9072 chunks total
#define CHBYTES 65536u

typedef unsigned long long u64;

#define PK2(d, lo, hi) asm("mov.b64 %0, {%1, %2};" : "=l"(d) : "f"(lo), "f"(hi))
#define UPK2(lo, hi, s) asm("mov.b64 {%0, %1}, %2;" : "=f"(lo), "=f"(hi) : "l"(s))
#define FMA2(d, a, b, c) asm("fma.rn.f32x2 %0, %1, %2, %3;" : "=l"(d) : "l"(a), "l"(b), "l"(c))
#define ADD2(d, a, b) asm("add.rn.f32x2 %0, %1, %2;" : "=l"(d) : "l"(a), "l"(b))

__device__ float g_W0t[128 * H_];     // [k<128][j<256], k>=112 zero  (2 chunks)
__device__ float g_W1t[H_ * H_];      // (4 chunks)
__device__ float g_W2t[H_ * H_];      // (4 chunks)
__device__ float g_W3t[H_ * 128];     // [k<256][j<128], cols>=96 zero (2 chunks)

__constant__ float cAT[6][5] = {
    {0.f, 0.f, 0.f, 0.f, 0.f},
    {1.0f / 5.0f, 0.f, 0.f, 0.f, 0.f},
    {3.0f / 40.0f, 9.0f / 40.0f, 0.f, 0.f, 0.f},
    {44.0f / 45.0f, -56.0f / 15.0f, 32.0f / 9.0f, 0.f, 0.f},
    {19372.0f / 6561.0f, -25360.0f / 2187.0f, 64448.0f / 6561.0f, -212.0f / 729.0f, 0.f},
    {9017.0f / 3168.0f, -355.0f / 33.0f, 46732.0f / 5247.0f, 49.0f / 176.0f, -5103.0f / 18656.0f}
};
__constant__ float cB[6] = {
    35.0f / 384.0f, 0.0f, 500.0f / 1113.0f, 125.0f / 192.0f,
    -2187.0f / 6784.0f, 11.0f / 84.0f
};

__global__ void transpose_k(const float* __restrict__ W0, const float* __restrict__ W1,
                            const float* __restrict__ W2, const float* __restrict__ W3) {
    int i = blockIdx.x * blockDim.x + threadIdx.x;
    if (i < 128 * H_)  { int k = i >> 8, j = i & 255;
                         g_W0t[i] = (k < IN_) ? W0[j * IN_ + k] : 0.0f; }
    if (i < H_ * H_)   { int j = i >> 8, k = i & 255;   g_W1t[k * H_ + j] = W1[i];
                                                        g_W2t[k * H_ + j] = W2[i]; }
    if (i < H_ * 128)  { int k = i >> 7, j = i & 127;
                         g_W3t[k * 128 + j] = (j < OUT_) ? W3[j * H_ + k] : 0.0f; }
}

struct __align__(16) Smem {
    u64   wbuf[2][8192];      // 128KB: weight stream double buffer
    u64   spart[4096];        // 32KB spill
    u64   shA [RP_ * XS];
    u64   shB [RP_ * XS];
    u64   sxs [RP_ * XS];
    u64   sy  [512];
    u64   sks [6 * 512];
    u64   sacs[12 * 64];
    u64   mbar[2];
    u64   srctab[12];
    u64   shh2[RP_];
    float shh [R_];
    float stimes[R_ * T_];
    int   sidx[12 * R_];
    float sb0[256], sb1[256], sb2[256], sb3[96];
};

__device__ __forceinline__ uint32_t smem_u32(const void* p) {
    uint32_t a;
    asm("{ .reg .u64 t; cvta.to.shared.u64 t, %1; cvt.u32.u64 %0, t; }" : "=r"(a) : "l"(p));
    return a;
}

__device__ __forceinline__ void issue_chunk(Smem* sm, int srcidx, int buf) {
    uint32_t mb = smem_u32(&sm->mbar[buf]);
    asm volatile("mbarrier.arrive.expect_tx.shared.b64 _, [%0], %1;"
                 :: "r"(mb), "r"(CHBYTES) : "memory");
    uint32_t dst = smem_u32(&sm->wbuf[buf][0]);
    u64 src = sm->srctab[srcidx];
    asm volatile("cp.async.bulk.shared::cluster.global.mbarrier::complete_tx::bytes "
                 "[%0], [%1], %2, [%3];"
                 :: "r"(dst), "l"(src), "r"(CHBYTES), "r"(mb) : "memory");
}

__device__ __forceinline__ void wait_full(Smem* sm, int buf, int parity) {
    uint32_t mb = smem_u32(&sm->mbar[buf]);
    uint32_t done;
    asm volatile("{\n\t.reg .pred p;\n\t"
        "mbarrier.try_wait.parity.acquire.cta.shared::cta.b64 p, [%1], %2;\n\t"
        "selp.b32 %0, 1, 0, p;\n\t}"
        : "=r"(done) : "r"(mb), "r"((uint32_t)parity) : "memory");
    if (!done) {
        asm volatile("{\n\t.reg .pred P1;\n\t"
            "WL%=:\n\t"
            "mbarrier.try_wait.parity.acquire.cta.shared::cta.b64 P1, [%0], %1, 0x989680;\n\t"
            "@P1 bra.uni WD%=;\n\t"
            "bra.uni WL%=;\n\t"
            "WD%=:\n\t}"
            :: "r"(mb), "r"((uint32_t)parity) : "memory");
    }
}

// Advance stream by one chunk: wait data, return buf; caller computes, then
// calls stream_close (sync + issue next).
#define STREAM_OPEN(bufv)                                                     \
    const int bufv = sabs & 1;                                                \
    { const int par = bufv ? ph1 : ph0;                                       \
      wait_full(sm, bufv, par);                                               \
      if (bufv) ph1 ^= 1; else ph0 ^= 1; }

#define STREAM_CLOSE(bufv)                                                    \
    __syncthreads();                                                          \
    if (nissued < NCHTOT) {                                                   \
        if (tid == 0) issue_chunk(sm, isrc, bufv);                            \
        nissued++; isrc++; if (isrc == 12) isrc = 0;                          \
    }                                                                         \
    sabs++;

// Hidden layer (N=256, K = nch*64): KG=4 x CG=64(C=4) x RPH=2, streamed.
__device__ __forceinline__ void hidden_stream(
    Smem* sm, int nch, const u64* __restrict__ xin,
    const float* __restrict__ sb, u64* __restrict__ xout,
    int tid, int kg, int lane128,
    int& sabs, int& ph0, int& ph1, int& isrc, int& nissued) {
    const int cg = lane128 >> 1, rph = lane128 & 1;
    const int col0 = cg * 4;
    const int klocal0 = kg * 16;
    u64 a00 = 0, a01 = 0, a10 = 0, a11 = 0, a20 = 0, a21 = 0, a30 = 0, a31 = 0;
    for (int c = 0; c < nch; c++) {
        STREAM_OPEN(buf)
        const float* wp = (const float*)sm->wbuf[buf] + klocal0 * H_ + col0;
        const int xk = c * 64 + klocal0;
        const u64* xp0 = xin + (rph * 2)     * XS + xk;
        const u64* xp1 = xin + (rph * 2 + 1) * XS + xk;
#pragma unroll
        for (int kk = 0; kk < 16; kk += 2) {
            const float4 wA = *(const float4*)(wp + kk * H_);
            const float4 wB = *(const float4*)(wp + (kk + 1) * H_);
            u64 wA0, wA1, wA2, wA3, wB0, wB1, wB2, wB3;
            PK2(wA0, wA.x, wA.x); PK2(wA1, wA.y, wA.y);
            PK2(wA2, wA.z, wA.z); PK2(wA3, wA.w, wA.w);
            PK2(wB0, wB.x, wB.x); PK2(wB1, wB.y, wB.y);
            PK2(wB2, wB.z, wB.z); PK2(wB3, wB.w, wB.w);
            const ulonglong2 x0 = *(const ulonglong2*)(xp0 + kk);
            const ulonglong2 x1 = *(const ulonglong2*)(xp1 + kk);
            FMA2(a00, wA0, x0.x, a00); FMA2(a00, wB0, x0.y, a00);
            FMA2(a01, wA0, x1.x, a01); FMA2(a01, wB0, x1.y, a01);
            FMA2(a10, wA1, x0.x, a10); FMA2(a10, wB1, x0.y, a10);
            FMA2(a11, wA1, x1.x, a11); FMA2(a11, wB1, x1.y, a11);
            FMA2(a20, wA2, x0.x, a20); FMA2(a20, wB2, x0.y, a20);
            FMA2(a21, wA2, x1.x, a21); FMA2(a21, wB2, x1.y, a21);
            FMA2(a30, wA3, x0.x, a30); FMA2(a30, wB3, x0.y, a30);
            FMA2(a31, wA3, x1.x, a31); FMA2(a31, wB3, x1.y, a31);
        }
        if (c == nch - 1) {                       // spill before the chunk sync
            u64* spk = sm->spart + kg * 1024 + lane128;
            spk[0 * 128] = a00; spk[1 * 128] = a01;
            spk[2 * 128] = a10; spk[3 * 128] = a11;
            spk[4 * 128] = a20; spk[5 * 128] = a21;
            spk[6 * 128] = a30; spk[7 * 128] = a31;
        }
        STREAM_CLOSE(buf)
    }
    // Distributed reduce: 1024 outputs / 512 threads
    u64* const sp = sm->spart;
#pragma unroll
    for (int oi = 0; oi < 2; oi++) {
        const int o = tid + oi * 512;
        u64 v = sp[o];
        ADD2(v, v, sp[o + 1024]);
        ADD2(v, v, sp[o + 2048]);
        ADD2(v, v, sp[o + 3072]);
        const int c2i = o >> 7, l = o & 127;
        const int c = c2i >> 1, i = c2i & 1;
        const int col = (l >> 1) * 4 + c, rp = (l & 1) * 2 + i;
        const float b = sb[col];
        float v0, v1; UPK2(v0, v1, v);
        v0 = fmaxf(v0 + b, 0.f); v1 = fmaxf(v1 + b, 0.f);
        ((float2*)xout)[rp * XS + col] = make_float2(v0, v1);
    }
    __syncthreads();
}

// Output layer (N pad 128, K=256, 2 chunks of 128 k): KG=4 x CG=64(C=2) x
// RPH=2, streamed, fused Dopri5 epilogue.
__device__ __forceinline__ void out_stream(
    Smem* sm, const u64* __restrict__ xin,
    int s, int sub, int j, int row0, float* __restrict__ out,
    int tid, int kg, int lane128,
    int& sabs, int& ph0, int& ph1, int& isrc, int& nissued) {
    const int cg = lane128 >> 1, rph = lane128 & 1;
    const int col0 = cg * 2;
    const int klocal0 = kg * 32;
    u64 a00 = 0, a01 = 0, a10 = 0, a11 = 0;
    for (int c = 0; c < 2; c++) {
        STREAM_OPEN(buf)
        const float* wp = (const float*)sm->wbuf[buf] + klocal0 * 128 + col0;
        const int xk = c * 128 + klocal0;
        const u64* xp0 = xin + (rph * 2)     * XS + xk;
        const u64* xp1 = xin + (rph * 2 + 1) * XS + xk;
#pragma unroll
        for (int kk = 0; kk < 32; kk += 2) {
            const float2 wA = *(const float2*)(wp + kk * 128);
            const float2 wB = *(const float2*)(wp + (kk + 1) * 128);
            u64 wA0, wA1, wB0, wB1;
            PK2(wA0, wA.x, wA.x); PK2(wA1, wA.y, wA.y);
            PK2(wB0, wB.x, wB.x); PK2(wB1, wB.y, wB.y);
            const ulonglong2 x0 = *(const ulonglong2*)(xp0 + kk);
            const ulonglong2 x1 = *(const ulonglong2*)(xp1 + kk);
            FMA2(a00, wA0, x0.x, a00); FMA2(a00, wB0, x0.y, a00);
            FMA2(a01, wA0, x1.x, a01); FMA2(a01, wB0, x1.y, a01);
            FMA2(a10, wA1, x0.x, a10); FMA2(a10, wB1, x0.y, a10);
            FMA2(a11, wA1, x1.x, a11); FMA2(a11, wB1, x1.y, a11);
        }
        if (c == 1) {
            u64* spk = sm->spart + kg * 512 + lane128;
            spk[0 * 128] = a00; spk[1 * 128] = a01;
            spk[2 * 128] = a10; spk[3 * 128] = a11;
        }
        STREAM_CLOSE(buf)
    }
    // Reduce + fused Dopri5 epilogue (one output per thread)
    u64* const sp = sm->spart;
    const int o = tid;
    u64 v = sp[o];
    ADD2(v, v, sp[o + 512]);
    ADD2(v, v, sp[o + 1024]);
    ADD2(v, v, sp[o + 1536]);
    const int c2i = o >> 6, l = o & 63;
    // spill layout: sp[kg*512 + (c*2... rows are (cidx*2+i)*128? For output:
    // rows 0..3 at stride 128 hold (c,i) = (0,0),(0,1),(1,0),(1,1) over 128 lanes
    // o = row*128 + lane128 -> row = o>>7, lane = o&127
    const int row = o >> 7, lane = o & 127;
    const int cc = row >> 1, ii = row & 1;
    const int col = (lane >> 1) * 2 + cc, rp = (lane & 1) * 2 + ii;
    (void)c2i; (void)l;
    u64* const sks64 = sm->sks;
    u64* const sy64  = sm->sy;
    u64* const sxs64 = sm->sxs;
    const u64* const sacs64 = sm->sacs;

    if (col < OUT_) {
        const int o2 = rp * 128 + col;
        u64 bp; { const float b = sm->sb3[col]; PK2(bp, b, b); }
        u64 kn; ADD2(kn, v, bp);
        sks64[s * 512 + o2] = kn;
        const u64 y  = sy64[o2];
        const u64 hh = sm->shh2[rp];
        const u64 z = 0ull;
        if (s < 5) {
            u64 sum, ap;
            { const float a = cAT[s + 1][s]; PK2(ap, a, a); }
            FMA2(sum, ap, kn, z);
            for (int i2 = 0; i2 < s; i2++) {
                const float a = cAT[s + 1][i2]; PK2(ap, a, a);
                FMA2(sum, ap, sks64[i2 * 512 + o2], sum);
            }
            u64 x; FMA2(x, hh, sum, y);
            sxs64[rp * XS + col] = x;
        } else {
            u64 sum, ap;
            { const float a = cB[5]; PK2(ap, a, a); }
            FMA2(sum, ap, kn, z);
            { const float a = cB[4]; PK2(ap, a, a); FMA2(sum, ap, sks64[4 * 512 + o2], sum); }
            { const float a = cB[3]; PK2(ap, a, a); FMA2(sum, ap, sks64[3 * 512 + o2], sum); }
            { const float a = cB[2]; PK2(ap, a, a); FMA2(sum, ap, sks64[2 * 512 + o2], sum); }
            { const float a = cB[0]; PK2(ap, a, a); FMA2(sum, ap, sks64[0 * 512 + o2], sum); }
            u64 yn; FMA2(yn, hh, sum, y);
            sy64[o2] = yn;
            sxs64[rp * XS + col] = yn;
            if (sub == 1 && col < OB_) {
                float y0, y1; UPK2(y0, y1, yn);
                const size_t base = (size_t)(row0 + rp * 2) * T_ * OB_ +
                                    (size_t)(j + 1) * OB_ + col;
                out[base] = y0;
                out[base + (size_t)T_ * OB_] = y1;
            }
        }
    } else if (col < IN_) {
        const int s12n = (s < 5) ? (sub * 6 + s + 1) : ((sub == 0) ? 6 : -1);
        if (s12n >= 0)
            sxs64[rp * XS + col] = sacs64[s12n * 64 + rp * 16 + (col - OUT_)];
    }
    __syncthreads();
}

__global__ void __launch_bounds__(NTHR, 1)
node_kernel(const float* __restrict__ ob, const float* __restrict__ acs,
            const float* __restrict__ times,
            const float* __restrict__ b0, const float* __restrict__ b1,
            const float* __restrict__ b2, const float* __restrict__ b3,
            float* __restrict__ out) {
    extern __shared__ __align__(16) char smem_raw[];
    Smem* sm = reinterpret_cast<Smem*>(smem_raw);

    const int tid  = threadIdx.x;
    const int kg   = tid >> 7;
    const int l128 = tid & 127;
    const int row0 = blockIdx.x * R_;

    // Biases, times, srctab, mbarrier init
    if (tid < 256) { sm->sb0[tid] = b0[tid]; sm->sb1[tid] = b1[tid]; sm->sb2[tid] = b2[tid]; }
    if (tid < OUT_) sm->sb3[tid] = b3[tid];
    sm->stimes[tid] = times[(size_t)(row0 + (tid >> 6)) * T_ + (tid & 63)];
    if (tid < 12) {
        const float* p;
        if      (tid < 2)  p = g_W0t + tid * 16384;
        else if (tid < 6)  p = g_W1t + (tid - 2) * 16384;
        else if (tid < 10) p = g_W2t + (tid - 6) * 16384;
        else               p = g_W3t + (tid - 10) * 16384;
        sm->srctab[tid] = (u64)p;
    }
    if (tid == 0) {
        uint32_t mb0 = smem_u32(&sm->mbar[0]);
        uint32_t mb1 = smem_u32(&sm->mbar[1]);
        asm volatile("mbarrier.init.shared.b64 [%0], 1;" :: "r"(mb0) : "memory");
        asm volatile("mbarrier.init.shared.b64 [%0], 1;" :: "r"(mb1) : "memory");
    }
    // Init sy + emit t=0; zero sxs K-pad
    {
        const int col = tid & 127, rp = tid >> 7;
        const int r0 = row0 + rp * 2;
        float v0 = 0.f, v1 = 0.f;
        if (col < OB_) {
            v0 = ob[r0 * OB_ + col];
            v1 = ob[(r0 + 1) * OB_ + col];
            out[(size_t)r0 * T_ * OB_ + col] = v0;
            out[(size_t)(r0 + 1) * T_ * OB_ + col] = v1;
        }
        u64 p; PK2(p, v0, v1);
        sm->sy[tid] = p;
        if (col >= IN_) sm->sxs[rp * XS + col] = 0ull;
    }
    __syncthreads();

    // Stream prologue: issue chunks 0 and 1
    if (tid == 0) { issue_chunk(sm, 0, 0); issue_chunk(sm, 1, 1); }
    int sabs = 0, ph0 = 0, ph1 = 0, isrc = 2, nissued = 2;

    for (int j = 0; j < T_ - 1; j++) {
        // Interval prologue: parallel searchsorted (96 threads)
        if (tid < 96) {
            const int s12 = tid >> 3, r = tid & 7;
            const float* tsr = &sm->stimes[r * 64];
            const float t0 = tsr[j], t1 = tsr[j + 1];
            const float h = (t1 - t0) / 2.0f;
            if (s12 == 0) sm->shh[r] = h;
            const int sub = (s12 >= 6) ? 1 : 0;
            const int s = s12 - sub * 6;
            const float t = t0 + (float)sub * h;
            float st;
            if      (s == 0) st = t;
            else if (s == 1) st = t + h / 5.0f;
            else if (s == 2) st = t + (3.0f * h) / 10.0f;
            else if (s == 3) st = t + (4.0f * h) / 5.0f;
            else if (s == 4) st = t + (8.0f * h) / 9.0f;
            else             st = t + h;
            int cnt = 0;
            for (int i = 0; i < T_; i++) cnt += (tsr[i] <= st) ? 1 : 0;
            int ai = cnt - 1;
            ai = max(0, min(ai, T_ - 1));
            sm->sidx[s12 * R_ + r] = ai;
        }
        __syncthreads();
        if (tid < RP_) {
            u64 p; PK2(p, sm->shh[tid * 2], sm->shh[tid * 2 + 1]);
            sm->shh2[tid] = p;
        }
        for (int idx = tid; idx < 12 * RP_ * AC_ * 2; idx += NTHR) {
            const int s12 = idx >> 7;
            const int rem = idx & 127;
            const int rp = rem >> 5, rem2 = rem & 31;
            const int c = rem2 >> 1, p = rem2 & 1, r = rp * 2 + p;
            ((float*)sm->sacs)[s12 * 128 + rp * 32 + c * 2 + p] =
                acs[(size_t)(row0 + r) * T_ * AC_ +
                    (size_t)sm->sidx[s12 * R_ + r] * AC_ + c];
        }
        __syncthreads();
        {
            const int col = tid & 127, rp = tid >> 7;
            if (col < OUT_)
                sm->sxs[rp * XS + col] = sm->sy[tid];
            else if (col < IN_)
                sm->sxs[rp * XS + col] = sm->sacs[rp * 16 + (col - OUT_)];
        }
        __syncthreads();

        for (int sub = 0; sub < 2; sub++) {
            for (int s = 0; s < 6; s++) {
                hidden_stream(sm, 2, sm->sxs, sm->sb0, sm->shA,
                              tid, kg, l128, sabs, ph0, ph1, isrc, nissued);
                hidden_stream(sm, 4, sm->shA, sm->sb1, sm->shB,
                              tid, kg, l128, sabs, ph0, ph1, isrc, nissued);
                hidden_stream(sm, 4, sm->shB, sm->sb2, sm->shA,
                              tid, kg, l128, sabs, ph0, ph1, isrc, nissued);
                out_stream(sm, sm->shA, s, sub, j, row0, out,
                           tid, kg, l128, sabs, ph0, ph1, isrc, nissued);
            }
        }
    }
}

extern "C" void kernel_launch(void* const* d_in, const int* in_sizes, int n_in,
                              void* d_out, int out_size) {
    const float* ob    = (const float*)d_in[0];
    const float* acs   = (const float*)d_in[1];
    const float* times = (const float*)d_in[2];
    const float* W0    = (const float*)d_in[3];
    const float* b0    = (const float*)d_in[4];
    const float* W1    = (const float*)d_in[5];
    const float* b1    = (const float*)d_in[6];
    const float* W2    = (const float*)d_in[7];
    const float* b2    = (const float*)d_in[8];
    const float* W3    = (const float*)d_in[9];
    const float* b3    = (const float*)d_in[10];
    float* out = (float*)d_out;

    cudaFuncSetAttribute(node_kernel,
                         cudaFuncAttributeMaxDynamicSharedMemorySize,
                         (int)sizeof(Smem));

    transpose_k<<<256, 256>>>(W0, W1, W2, W3);
    node_kernel<<<NCTA, NTHR, sizeof(Smem)>>>(ob, acs, times, b0, b1, b2, b3, out);
}

// round 15
// speedup vs baseline: 2.2210x; 1.0728x over previous
#include <cuda_runtime.h>
#include <cstdint>

// ---------------------------------------------------------------------------
// NeuralODE (Dopri5) — round 14: producer-only TMA buffer recycling.
// = round 13 (TMA-streamed weights, packed fp32, fused epilogue) with the
// per-chunk CTA-wide __syncthreads replaced by bar.arrive (compute warps) +
// bar.sync (warp 0 only) + fence.proxy.async before re-issue. Full barriers
// per eval: 16 -> 8 (4 spill-sync doubling as last-chunk recycle + 4 out).
// Math untouched -> numerics identical to round 13.
// ---------------------------------------------------------------------------

#define B_    1024
#define T_    64
#define OB_   64
#define AC_   16
#define H_    256
#define IN_   112
#define OUT_  96
#define R_    8
#define RP_   4
#define NCTA  (B_ / R_)
#define NTHR  512
#define XS    260
#define NEVAL (63 * 12)
#define NCHTOT (NEVAL * 12)
#define CHBYTES 65536u

typedef unsigned long long u64;

#define PK2(d, lo, hi) asm("mov.b64 %0, {%1, %2};" : "=l"(d) : "f"(lo), "f"(hi))
#define UPK2(lo, hi, s) asm("mov.b64 {%0, %1}, %2;" : "=f"(lo), "=f"(hi) : "l"(s))
#define FMA2(d, a, b, c) asm("fma.rn.f32x2 %0, %1, %2, %3;" : "=l"(d) : "l"(a), "l"(b), "l"(c))
#define ADD2(d, a, b) asm("add.rn.f32x2 %0, %1, %2;" : "=l"(d) : "l"(a), "l"(b))

__device__ float g_W0t[128 * H_];     // [k<128][j<256], k>=112 zero  (2 chunks)
__device__ float g_W1t[H_ * H_];      // (4 chunks)
__device__ float g_W2t[H_ * H_];      // (4 chunks)
__device__ float g_W3t[H_ * 128];     // [k<256][j<128], cols>=96 zero (2 chunks)

__constant__ float cAT[6][5] = {
    {0.f, 0.f, 0.f, 0.f, 0.f},
    {1.0f / 5.0f, 0.f, 0.f, 0.f, 0.f},
    {3.0f / 40.0f, 9.0f / 40.0f, 0.f, 0.f, 0.f},
    {44.0f / 45.0f, -56.0f / 15.0f, 32.0f / 9.0f, 0.f, 0.f},
    {19372.0f / 6561.0f, -25360.0f / 2187.0f, 64448.0f / 6561.0f, -212.0f / 729.0f, 0.f},
    {9017.0f / 3168.0f, -355.0f / 33.0f, 46732.0f / 5247.0f, 49.0f / 176.0f, -5103.0f / 18656.0f}
};
__constant__ float cB[6] = {
    35.0f / 384.0f, 0.0f, 500.0f / 1113.0f, 125.0f / 192.0f,
    -2187.0f / 6784.0f, 11.0f / 84.0f
};

__global__ void transpose_k(const float* __restrict__ W0, const float* __restrict__ W1,
                            const float* __restrict__ W2, const float* __restrict__ W3) {
    int i = blockIdx.x * blockDim.x + threadIdx.x;
    if (i < 128 * H_)  { int k = i >> 8, j = i & 255;
                         g_W0t[i] = (k < IN_) ? W0[j * IN_ + k] : 0.0f; }
    if (i < H_ * H_)   { int j = i >> 8, k = i & 255;   g_W1t[k * H_ + j] = W1[i];
                                                        g_W2t[k * H_ + j] = W2[i]; }
    if (i < H_ * 128)  { int k = i >> 7, j = i & 127;
                         g_W3t[k * 128 + j] = (j < OUT_) ? W3[j * H_ + k] : 0.0f; }
}

struct __align__(16) Smem {
    u64   wbuf[2][8192];      // 128KB weight stream double buffer
    u64   spart[4096];        // 32KB spill
    u64   shA [RP_ * XS];
    u64   shB [RP_ * XS];
    u64   sxs [RP_ * XS];
    u64   sy  [512];
    u64   sks [6 * 512];
    u64   sacs[12 * 64];
    u64   mbar[2];
    u64   srctab[12];
    u64   shh2[RP_];
    float shh [R_];
    float stimes[R_ * T_];
    int   sidx[12 * R_];
    float sb0[256], sb1[256], sb2[256], sb3[96];
};

__device__ __forceinline__ uint32_t smem_u32(const void* p) {
    uint32_t a;
    asm("{ .reg .u64 t; cvta.to.shared.u64 t, %1; cvt.u32.u64 %0, t; }" : "=r"(a) : "l"(p));
    return a;
}

__device__ __forceinline__ void issue_chunk(Smem* sm, int srcidx, int buf) {
    uint32_t mb = smem_u32(&sm->mbar[buf]);
    asm volatile("mbarrier.arrive.expect_tx.shared.b64 _, [%0], %1;"
                 :: "r"(mb), "r"(CHBYTES) : "memory");
    uint32_t dst = smem_u32(&sm->wbuf[buf][0]);
    u64 src = sm->srctab[srcidx];
    asm volatile("cp.async.bulk.shared::cluster.global.mbarrier::complete_tx::bytes "
                 "[%0], [%1], %2, [%3];"
                 :: "r"(dst), "l"(src), "r"(CHBYTES), "r"(mb) : "memory");
}

__device__ __forceinline__ void wait_full(Smem* sm, int buf, int parity) {
    uint32_t mb = smem_u32(&sm->mbar[buf]);
    uint32_t done;
    asm volatile("{\n\t.reg .pred p;\n\t"
        "mbarrier.try_wait.parity.acquire.cta.shared::cta.b64 p, [%1], %2;\n\t"
        "selp.b32 %0, 1, 0, p;\n\t}"
        : "=r"(done) : "r"(mb), "r"((uint32_t)parity) : "memory");
    if (!done) {
        asm volatile("{\n\t.reg .pred P1;\n\t"
            "WL%=:\n\t"
            "mbarrier.try_wait.parity.acquire.cta.shared::cta.b64 P1, [%0], %1, 0x989680;\n\t"
            "@P1 bra.uni WD%=;\n\t"
            "bra.uni WL%=;\n\t"
            "WD%=:\n\t}"
            :: "r"(mb), "r"((uint32_t)parity) : "memory");
    }
}

#define STREAM_OPEN(bufv)                                                     \
    const int bufv = sabs & 1;                                                \
    { const int par = bufv ? ph1 : ph0;                                       \
      wait_full(sm, bufv, par);                                               \
      if (bufv) ph1 ^= 1; else ph0 ^= 1; }

// Fast close (non-last chunk): compute warps arrive and move on; only warp 0
// waits for full drain, fences generic->async, and re-issues the buffer.
#define STREAM_CLOSE_FAST(bufv)                                               \
    { const int barid = 1 + (sabs & 1);                                       \
      if (tid < 32) {                                                         \
          asm volatile("bar.sync %0, %1;" :: "r"(barid), "r"(NTHR) : "memory"); \
          if (tid == 0 && nissued < NCHTOT) {                                 \
              asm volatile("fence.proxy.async.shared::cta;" ::: "memory");    \
              issue_chunk(sm, isrc, bufv);                                    \
          }                                                                   \
      } else {                                                                \
          asm volatile("bar.arrive %0, %1;" :: "r"(barid), "r"(NTHR) : "memory"); \
      }                                                                       \
      if (nissued < NCHTOT) { nissued++; isrc = (isrc == 11) ? 0 : isrc + 1; } \
      sabs++; }

// Full close (last chunk of a layer): the __syncthreads doubles as the
// spill -> reduce barrier; warp 0 re-issues after it.
#define STREAM_CLOSE_FULL(bufv)                                               \
    __syncthreads();                                                          \
    if (tid == 0 && nissued < NCHTOT) {                                       \
        asm volatile("fence.proxy.async.shared::cta;" ::: "memory");          \
        issue_chunk(sm, isrc, bufv);                                          \
    }                                                                         \
    if (nissued < NCHTOT) { nissued++; isrc = (isrc == 11) ? 0 : isrc + 1; }  \
    sabs++;

// Hidden layer (N=256, K = nch*64): KG=4 x CG=64(C=4) x RPH=2, streamed.
__device__ __forceinline__ void hidden_stream(
    Smem* sm, int nch, const u64* __restrict__ xin,
    const float* __restrict__ sb, u64* __restrict__ xout,
    int tid, int kg, int lane128,
    int& sabs, int& ph0, int& ph1, int& isrc, int& nissued) {
    const int cg = lane128 >> 1, rph = lane128 & 1;
    const int col0 = cg * 4;
    const int klocal0 = kg * 16;
    u64 a00 = 0, a01 = 0, a10 = 0, a11 = 0, a20 = 0, a21 = 0, a30 = 0, a31 = 0;
    for (int c = 0; c < nch; c++) {
        STREAM_OPEN(buf)
        const float* wp = (const float*)sm->wbuf[buf] + klocal0 * H_ + col0;
        const int xk = c * 64 + klocal0;
        const u64* xp0 = xin + (rph * 2)     * XS + xk;
        const u64* xp1 = xin + (rph * 2 + 1) * XS + xk;
#pragma unroll
        for (int kk = 0; kk < 16; kk += 2) {
            const float4 wA = *(const float4*)(wp + kk * H_);
            const float4 wB = *(const float4*)(wp + (kk + 1) * H_);
            u64 wA0, wA1, wA2, wA3, wB0, wB1, wB2, wB3;
            PK2(wA0, wA.x, wA.x); PK2(wA1, wA.y, wA.y);
            PK2(wA2, wA.z, wA.z); PK2(wA3, wA.w, wA.w);
            PK2(wB0, wB.x, wB.x); PK2(wB1, wB.y, wB.y);
            PK2(wB2, wB.z, wB.z); PK2(wB3, wB.w, wB.w);
            const ulonglong2 x0 = *(const ulonglong2*)(xp0 + kk);
            const ulonglong2 x1 = *(const ulonglong2*)(xp1 + kk);
            FMA2(a00, wA0, x0.x, a00); FMA2(a00, wB0, x0.y, a00);
            FMA2(a01, wA0, x1.x, a01); FMA2(a01, wB0, x1.y, a01);
            FMA2(a10, wA1, x0.x, a10); FMA2(a10, wB1, x0.y, a10);
            FMA2(a11, wA1, x1.x, a11); FMA2(a11, wB1, x1.y, a11);
            FMA2(a20, wA2, x0.x, a20); FMA2(a20, wB2, x0.y, a20);
            FMA2(a21, wA2, x1.x, a21); FMA2(a21, wB2, x1.y, a21);
            FMA2(a30, wA3, x0.x, a30); FMA2(a30, wB3, x0.y, a30);
            FMA2(a31, wA3, x1.x, a31); FMA2(a31, wB3, x1.y, a31);
        }
        if (c < nch - 1) {
            STREAM_CLOSE_FAST(buf)
        } else {
            // Spill, then full sync (serves buffer recycle + spill barrier)
            u64* spk = sm->spart + kg * 1024 + lane128;
            spk[0 * 128] = a00; spk[1 * 128] = a01;
            spk[2 * 128] = a10; spk[3 * 128] = a11;
            spk[4 * 128] = a20; spk[5 * 128] = a21;
            spk[6 * 128] = a30; spk[7 * 128] = a31;
            STREAM_CLOSE_FULL(buf)
        }
    }
    // Distributed reduce: 1024 outputs / 512 threads
    u64* const sp = sm->spart;
#pragma unroll
    for (int oi = 0; oi < 2; oi++) {
        const int o = tid + oi * 512;
        u64 v = sp[o];
        ADD2(v, v, sp[o + 1024]);
        ADD2(v, v, sp[o + 2048]);
        ADD2(v, v, sp[o + 3072]);
        const int c2i = o >> 7, l = o & 127;
        const int c = c2i >> 1, i = c2i & 1;
        const int col = (l >> 1) * 4 + c, rp = (l & 1) * 2 + i;
        const float b = sb[col];
        float v0, v1; UPK2(v0, v1, v);
        v0 = fmaxf(v0 + b, 0.f); v1 = fmaxf(v1 + b, 0.f);
        ((float2*)xout)[rp * XS + col] = make_float2(v0, v1);
    }
    __syncthreads();
}

// Output layer (N pad 128, K=256, 2 chunks): KG=4 x CG=64(C=2) x RPH=2,
// streamed, fused Dopri5 epilogue.
__device__ __forceinline__ void out_stream(
    Smem* sm, const u64* __restrict__ xin,
    int s, int sub, int j, int row0, float* __restrict__ out,
    int tid, int kg, int lane128,
    int& sabs, int& ph0, int& ph1, int& isrc, int& nissued) {
    const int cg = lane128 >> 1, rph = lane128 & 1;
    const int col0 = cg * 2;
    const int klocal0 = kg * 32;
    u64 a00 = 0, a01 = 0, a10 = 0, a11 = 0;
    for (int c = 0; c < 2; c++) {
        STREAM_OPEN(buf)
        const float* wp = (const float*)sm->wbuf[buf] + klocal0 * 128 + col0;
        const int xk = c * 128 + klocal0;
        const u64* xp0 = xin + (rph * 2)     * XS + xk;
        const u64* xp1 = xin + (rph * 2 + 1) * XS + xk;
#pragma unroll
        for (int kk = 0; kk < 32; kk += 2) {
            const float2 wA = *(const float2*)(wp + kk * 128);
            const float2 wB = *(const float2*)(wp + (kk + 1) * 128);
            u64 wA0, wA1, wB0, wB1;
            PK2(wA0, wA.x, wA.x); PK2(wA1, wA.y, wA.y);
            PK2(wB0, wB.x, wB.x); PK2(wB1, wB.y, wB.y);
            const ulonglong2 x0 = *(const ulonglong2*)(xp0 + kk);
            const ulonglong2 x1 = *(const ulonglong2*)(xp1 + kk);
            FMA2(a00, wA0, x0.x, a00); FMA2(a00, wB0, x0.y, a00);
            FMA2(a01, wA0, x1.x, a01); FMA2(a01, wB0, x1.y, a01);
            FMA2(a10, wA1, x0.x, a10); FMA2(a10, wB1, x0.y, a10);
            FMA2(a11, wA1, x1.x, a11); FMA2(a11, wB1, x1.y, a11);
        }
        if (c < 1) {
            STREAM_CLOSE_FAST(buf)
        } else {
            u64* spk = sm->spart + kg * 512 + lane128;
            spk[0 * 128] = a00; spk[1 * 128] = a01;
            spk[2 * 128] = a10; spk[3 * 128] = a11;
            STREAM_CLOSE_FULL(buf)
        }
    }
    // Reduce + fused Dopri5 epilogue (one output per thread)
    u64* const sp = sm->spart;
    const int o = tid;
    u64 v = sp[o];
    ADD2(v, v, sp[o + 512]);
    ADD2(v, v, sp[o + 1024]);
    ADD2(v, v, sp[o + 1536]);
    const int row = o >> 7, lane = o & 127;
    const int cc = row >> 1, ii = row & 1;
    const int col = (lane >> 1) * 2 + cc, rp = (lane & 1) * 2 + ii;
    u64* const sks64 = sm->sks;
    u64* const sy64  = sm->sy;
    u64* const sxs64 = sm->sxs;
    const u64* const sacs64 = sm->sacs;

    if (col < OUT_) {
        const int o2 = rp * 128 + col;
        u64 bp; { const float b = sm->sb3[col]; PK2(bp, b, b); }
        u64 kn; ADD2(kn, v, bp);
        sks64[s * 512 + o2] = kn;
        const u64 y  = sy64[o2];
        const u64 hh = sm->shh2[rp];
        const u64 z = 0ull;
        if (s < 5) {
            u64 sum, ap;
            { const float a = cAT[s + 1][s]; PK2(ap, a, a); }
            FMA2(sum, ap, kn, z);
            for (int i2 = 0; i2 < s; i2++) {
                const float a = cAT[s + 1][i2]; PK2(ap, a, a);
                FMA2(sum, ap, sks64[i2 * 512 + o2], sum);
            }
            u64 x; FMA2(x, hh, sum, y);
            sxs64[rp * XS + col] = x;
        } else {
            u64 sum, ap;
            { const float a = cB[5]; PK2(ap, a, a); }
            FMA2(sum, ap, kn, z);
            { const float a = cB[4]; PK2(ap, a, a); FMA2(sum, ap, sks64[4 * 512 + o2], sum); }
            { const float a = cB[3]; PK2(ap, a, a); FMA2(sum, ap, sks64[3 * 512 + o2], sum); }
            { const float a = cB[2]; PK2(ap, a, a); FMA2(sum, ap, sks64[2 * 512 + o2], sum); }
            { const float a = cB[0]; PK2(ap, a, a); FMA2(sum, ap, sks64[0 * 512 + o2], sum); }
            u64 yn; FMA2(yn, hh, sum, y);
            sy64[o2] = yn;
            sxs64[rp * XS + col] = yn;
            if (sub == 1 && col < OB_) {
                float y0, y1; UPK2(y0, y1, yn);
                const size_t base = (size_t)(row0 + rp * 2) * T_ * OB_ +
                                    (size_t)(j + 1) * OB_ + col;
                out[base] = y0;
                out[base + (size_t)T_ * OB_] = y1;
            }
        }
    } else if (col < IN_) {
        const int s12n = (s < 5) ? (sub * 6 + s + 1) : ((sub == 0) ? 6 : -1);
        if (s12n >= 0)
            sxs64[rp * XS + col] = sacs64[s12n * 64 + rp * 16 + (col - OUT_)];
    }
    __syncthreads();
}

__global__ void __launch_bounds__(NTHR, 1)
node_kernel(const float* __restrict__ ob, const float* __restrict__ acs,
            const float* __restrict__ times,
            const float* __restrict__ b0, const float* __restrict__ b1,
            const float* __restrict__ b2, const float* __restrict__ b3,
            float* __restrict__ out) {
    extern __shared__ __align__(16) char smem_raw[];
    Smem* sm = reinterpret_cast<Smem*>(smem_raw);

    const int tid  = threadIdx.x;
    const int kg   = tid >> 7;
    const int l128 = tid & 127;
    const int row0 = blockIdx.x * R_;

    if (tid < 256) { sm->sb0[tid] = b0[tid]; sm->sb1[tid] = b1[tid]; sm->sb2[tid] = b2[tid]; }
    if (tid < OUT_) sm->sb3[tid] = b3[tid];
    sm->stimes[tid] = times[(size_t)(row0 + (tid >> 6)) * T_ + (tid & 63)];
    if (tid < 12) {
        const float* p;
        if      (tid < 2)  p = g_W0t + tid * 16384;
        else if (tid < 6)  p = g_W1t + (tid - 2) * 16384;
        else if (tid < 10) p = g_W2t + (tid - 6) * 16384;
        else               p = g_W3t + (tid - 10) * 16384;
        sm->srctab[tid] = (u64)p;
    }
    if (tid == 0) {
        uint32_t mb0 = smem_u32(&sm->mbar[0]);
        uint32_t mb1 = smem_u32(&sm->mbar[1]);
        asm volatile("mbarrier.init.shared.b64 [%0], 1;" :: "r"(mb0) : "memory");
        asm volatile("mbarrier.init.shared.b64 [%0], 1;" :: "r"(mb1) : "memory");
    }
    {
        const int col = tid & 127, rp = tid >> 7;
        const int r0 = row0 + rp * 2;
        float v0 = 0.f, v1 = 0.f;
        if (col < OB_) {
            v0 = ob[r0 * OB_ + col];
            v1 = ob[(r0 + 1) * OB_ + col];
            out[(size_t)r0 * T_ * OB_ + col] = v0;
            out[(size_t)(r0 + 1) * T_ * OB_ + col] = v1;
        }
        u64 p; PK2(p, v0, v1);
        sm->sy[tid] = p;
        if (col >= IN_) sm->sxs[rp * XS + col] = 0ull;
    }
    __syncthreads();

    if (tid == 0) { issue_chunk(sm, 0, 0); issue_chunk(sm, 1, 1); }
    int sabs = 0, ph0 = 0, ph1 = 0, isrc = 2, nissued = 2;

    for (int j = 0; j < T_ - 1; j++) {
        if (tid < 96) {
            const int s12 = tid >> 3, r = tid & 7;
            const float* tsr = &sm->stimes[r * 64];
            const float t0 = tsr[j], t1 = tsr[j + 1];
            const float h = (t1 - t0) / 2.0f;
            if (s12 == 0) sm->shh[r] = h;
            const int sub = (s12 >= 6) ? 1 : 0;
            const int s = s12 - sub * 6;
            const float t = t0 + (float)sub * h;
            float st;
            if      (s == 0) st = t;
            else if (s == 1) st = t + h / 5.0f;
            else if (s == 2) st = t + (3.0f * h) / 10.0f;
            else if (s == 3) st = t + (4.0f * h) / 5.0f;
            else if (s == 4) st = t + (8.0f * h) / 9.0f;
            else             st = t + h;
            int cnt = 0;
            for (int i = 0; i < T_; i++) cnt += (tsr[i] <= st) ? 1 : 0;
            int ai = cnt - 1;
            ai = max(0, min(ai, T_ - 1));
            sm->sidx[s12 * R_ + r] = ai;
        }
        __syncthreads();
        if (tid < RP_) {
            u64 p; PK2(p, sm->shh[tid * 2], sm->shh[tid * 2 + 1]);
            sm->shh2[tid] = p;
        }
        for (int idx = tid; idx < 12 * RP_ * AC_ * 2; idx += NTHR) {
            const int s12 = idx >> 7;
            const int rem = idx & 127;
            const int rp = rem >> 5, rem2 = rem & 31;
            const int c = rem2 >> 1, p = rem2 & 1, r = rp * 2 + p;
            ((float*)sm->sacs)[s12 * 128 + rp * 32 + c * 2 + p] =
                acs[(size_t)(row0 + r) * T_ * AC_ +
                    (size_t)sm->sidx[s12 * R_ + r] * AC_ + c];
        }
        __syncthreads();
        {
            const int col = tid & 127, rp = tid >> 7;
            if (col < OUT_)
                sm->sxs[rp * XS + col] = sm->sy[tid];
            else if (col < IN_)
                sm->sxs[rp * XS + col] = sm->sacs[rp * 16 + (col - OUT_)];
        }
        __syncthreads();

        for (int sub = 0; sub < 2; sub++) {
            for (int s = 0; s < 6; s++) {
                hidden_stream(sm, 2, sm->sxs, sm->sb0, sm->shA,
                              tid, kg, l128, sabs, ph0, ph1, isrc, nissued);
                hidden_stream(sm, 4, sm->shA, sm->sb1, sm->shB,
                              tid, kg, l128, sabs, ph0, ph1, isrc, nissued);
                hidden_stream(sm, 4, sm->shB, sm->sb2, sm->shA,
                              tid, kg, l128, sabs, ph0, ph1, isrc, nissued);
                out_stream(sm, sm->shA, s, sub, j, row0, out,
                           tid, kg, l128, sabs, ph0, ph1, isrc, nissued);
            }
        }
    }
}

extern "C" void kernel_launch(void* const* d_in, const int* in_sizes, int n_in,
                              void* d_out, int out_size) {
    const float* ob    = (const float*)d_in[0];
    const float* acs   = (const float*)d_in[1];
    const float* times = (const float*)d_in[2];
    const float* W0    = (const float*)d_in[3];
    const float* b0    = (const float*)d_in[4];
    const float* W1    = (const float*)d_in[5];
    const float* b1    = (const float*)d_in[6];
    const float* W2    = (const float*)d_in[7];
    const float* b2    = (const float*)d_in[8];
    const float* W3    = (const float*)d_in[9];
    const float* b3    = (const float*)d_in[10];
    float* out = (float*)d_out;

    cudaFuncSetAttribute(node_kernel,
                         cudaFuncAttributeMaxDynamicSharedMemorySize,
                         (int)sizeof(Smem));

    transpose_k<<<256, 256>>>(W0, W1, W2, W3);
    node_kernel<<<NCTA, NTHR, sizeof(Smem)>>>(ob, acs, times, b0, b1, b2, b3, out);
}

// round 17
// speedup vs baseline: 2.3731x; 1.0685x over previous
#include <cuda_runtime.h>
#include <cstdint>

// ---------------------------------------------------------------------------
// NeuralODE (Dopri5) — round 16 (= round 15 resubmit after infra failure).
// Static TMA chunk schedule: 12 chunks/stage over 2 buffers => mbarrier
// parity state identical at every stage start; buf/parity/src/barid are
// compile-time functions of chunk position. Producer-only buffer recycling,
// packed fp32 FMA2, fused Dopri5 epilogue.
// Math untouched -> numerics identical (rel_err 1.228e-07).
// ---------------------------------------------------------------------------

#define B_    1024
#define T_    64
#define OB_   64
#define AC_   16
#define H_    256
#define IN_   112
#define OUT_  96
#define R_    8
#define RP_   4
#define NCTA  (B_ / R_)
#define NTHR  512
#define XS    260
#define CHBYTES 65536u

typedef unsigned long long u64;

#define PK2(d, lo, hi) asm("mov.b64 %0, {%1, %2};" : "=l"(d) : "f"(lo), "f"(hi))
#define UPK2(lo, hi, s) asm("mov.b64 {%0, %1}, %2;" : "=f"(lo), "=f"(hi) : "l"(s))
#define FMA2(d, a, b, c) asm("fma.rn.f32x2 %0, %1, %2, %3;" : "=l"(d) : "l"(a), "l"(b), "l"(c))
#define ADD2(d, a, b) asm("add.rn.f32x2 %0, %1, %2;" : "=l"(d) : "l"(a), "l"(b))

__device__ float g_W0t[128 * H_];     // [k<128][j<256], k>=112 zero  (chunks 0-1)
__device__ float g_W1t[H_ * H_];      // (chunks 2-5)
__device__ float g_W2t[H_ * H_];      // (chunks 6-9)
__device__ float g_W3t[H_ * 128];     // [k<256][j<128], cols>=96 zero (chunks 10-11)

__constant__ float cAT[6][5] = {
    {0.f, 0.f, 0.f, 0.f, 0.f},
    {1.0f / 5.0f, 0.f, 0.f, 0.f, 0.f},
    {3.0f / 40.0f, 9.0f / 40.0f, 0.f, 0.f, 0.f},
    {44.0f / 45.0f, -56.0f / 15.0f, 32.0f / 9.0f, 0.f, 0.f},
    {19372.0f / 6561.0f, -25360.0f / 2187.0f, 64448.0f / 6561.0f, -212.0f / 729.0f, 0.f},
    {9017.0f / 3168.0f, -355.0f / 33.0f, 46732.0f / 5247.0f, 49.0f / 176.0f, -5103.0f / 18656.0f}
};
__constant__ float cB[6] = {
    35.0f / 384.0f, 0.0f, 500.0f / 1113.0f, 125.0f / 192.0f,
    -2187.0f / 6784.0f, 11.0f / 84.0f
};

__global__ void transpose_k(const float* __restrict__ W0, const float* __restrict__ W1,
                            const float* __restrict__ W2, const float* __restrict__ W3) {
    int i = blockIdx.x * blockDim.x + threadIdx.x;
    if (i < 128 * H_)  { int k = i >> 8, j = i & 255;
                         g_W0t[i] = (k < IN_) ? W0[j * IN_ + k] : 0.0f; }
    if (i < H_ * H_)   { int j = i >> 8, k = i & 255;   g_W1t[k * H_ + j] = W1[i];
                                                        g_W2t[k * H_ + j] = W2[i]; }
    if (i < H_ * 128)  { int k = i >> 7, j = i & 127;
                         g_W3t[k * 128 + j] = (j < OUT_) ? W3[j * H_ + k] : 0.0f; }
}

struct __align__(16) Smem {
    u64   wbuf[2][8192];      // 128KB weight stream double buffer
    u64   spart[4096];        // 32KB spill
    u64   shA [RP_ * XS];
    u64   shB [RP_ * XS];
    u64   sxs [RP_ * XS];
    u64   sy  [512];
    u64   sks [6 * 512];
    u64   sacs[12 * 64];
    u64   mbar[2];
    u64   srctab[12];
    u64   shh2[RP_];
    float shh [R_];
    float stimes[R_ * T_];
    int   sidx[12 * R_];
    float sb0[256], sb1[256], sb2[256], sb3[96];
};

__device__ __forceinline__ uint32_t smem_u32(const void* p) {
    uint32_t a;
    asm("{ .reg .u64 t; cvta.to.shared.u64 t, %1; cvt.u32.u64 %0, t; }" : "=r"(a) : "l"(p));
    return a;
}

__device__ __forceinline__ void issue_chunk(Smem* sm, int srcidx, int buf) {
    uint32_t mb = smem_u32(&sm->mbar[buf]);
    asm volatile("mbarrier.arrive.expect_tx.shared.b64 _, [%0], %1;"
                 :: "r"(mb), "r"(CHBYTES) : "memory");
    uint32_t dst = smem_u32(&sm->wbuf[buf][0]);
    u64 src = sm->srctab[srcidx];
    asm volatile("cp.async.bulk.shared::cluster.global.mbarrier::complete_tx::bytes "
                 "[%0], [%1], %2, [%3];"
                 :: "r"(dst), "l"(src), "r"(CHBYTES), "r"(mb) : "memory");
}

__device__ __forceinline__ void wait_full(Smem* sm, int buf, int parity) {
    uint32_t mb = smem_u32(&sm->mbar[buf]);
    uint32_t done;
    asm volatile("{\n\t.reg .pred p;\n\t"
        "mbarrier.try_wait.parity.acquire.cta.shared::cta.b64 p, [%1], %2;\n\t"
        "selp.b32 %0, 1, 0, p;\n\t}"
        : "=r"(done) : "r"(mb), "r"((uint32_t)parity) : "memory");
    if (!done) {
        asm volatile("{\n\t.reg .pred P1;\n\t"
            "WL%=:\n\t"
            "mbarrier.try_wait.parity.acquire.cta.shared::cta.b64 P1, [%0], %1, 0x989680;\n\t"
            "@P1 bra.uni WD%=;\n\t"
            "bra.uni WL%=;\n\t"
            "WD%=:\n\t}"
            :: "r"(mb), "r"((uint32_t)parity) : "memory");
    }
}

// Static schedule: cpos = stage-local chunk position (0..11).
// buf = cpos&1, parity = (cpos>>1)&1, next src = cpos+2 (mod 12),
// named-barrier id = 1 + (cpos&1). All constant after unrolling.
#define SCHED_BUF(cpos)   ((cpos) & 1)
#define SCHED_PAR(cpos)   (((cpos) >> 1) & 1)
#define SCHED_NSRC(cpos)  ((cpos) >= 10 ? (cpos) - 10 : (cpos) + 2)

__device__ __forceinline__ void close_fast(Smem* sm, int tid, int cpos) {
    const int barid = 1 + (cpos & 1);
    if (tid < 32) {
        asm volatile("bar.sync %0, %1;" :: "r"(barid), "r"(NTHR) : "memory");
        if (tid == 0) {
            asm volatile("fence.proxy.async.shared::cta;" ::: "memory");
            issue_chunk(sm, SCHED_NSRC(cpos), SCHED_BUF(cpos));
        }
    } else {
        asm volatile("bar.arrive %0, %1;" :: "r"(barid), "r"(NTHR) : "memory");
    }
}

__device__ __forceinline__ void close_full(Smem* sm, int tid, int cpos, bool skip_issue) {
    __syncthreads();
    if (tid == 0 && !skip_issue) {
        asm volatile("fence.proxy.async.shared::cta;" ::: "memory");
        issue_chunk(sm, SCHED_NSRC(cpos), SCHED_BUF(cpos));
    }
}

// Hidden layer (N=256, K = NCH*64): KG=4 x CG=64(C=4) x RPH=2, streamed.
__device__ __forceinline__ void hidden_stream(
    Smem* sm, int cp0, int nch, const u64* __restrict__ xin,
    const float* __restrict__ sb, u64* __restrict__ xout,
    int tid, int kg, int lane128) {
    const int cg = lane128 >> 1, rph = lane128 & 1;
    const int col0 = cg * 4;
    const int klocal0 = kg * 16;
    u64 a00 = 0, a01 = 0, a10 = 0, a11 = 0, a20 = 0, a21 = 0, a30 = 0, a31 = 0;
#pragma unroll
    for (int c = 0; c < 4; c++) {
        if (c >= nch) break;
        const int cpos = cp0 + c;
        wait_full(sm, SCHED_BUF(cpos), SCHED_PAR(cpos));
        const float* wp = (const float*)sm->wbuf[SCHED_BUF(cpos)] + klocal0 * H_ + col0;
        const int xk = c * 64 + klocal0;
        const u64* xp0 = xin + (rph * 2)     * XS + xk;
        const u64* xp1 = xin + (rph * 2 + 1) * XS + xk;
#pragma unroll
        for (int kk = 0; kk < 16; kk += 2) {
            const float4 wA = *(const float4*)(wp + kk * H_);
            const float4 wB = *(const float4*)(wp + (kk + 1) * H_);
            u64 wA0, wA1, wA2, wA3, wB0, wB1, wB2, wB3;
            PK2(wA0, wA.x, wA.x); PK2(wA1, wA.y, wA.y);
            PK2(wA2, wA.z, wA.z); PK2(wA3, wA.w, wA.w);
            PK2(wB0, wB.x, wB.x); PK2(wB1, wB.y, wB.y);
            PK2(wB2, wB.z, wB.z); PK2(wB3, wB.w, wB.w);
            const ulonglong2 x0 = *(const ulonglong2*)(xp0 + kk);
            const ulonglong2 x1 = *(const ulonglong2*)(xp1 + kk);
            FMA2(a00, wA0, x0.x, a00); FMA2(a00, wB0, x0.y, a00);
            FMA2(a01, wA0, x1.x, a01); FMA2(a01, wB0, x1.y, a01);
            FMA2(a10, wA1, x0.x, a10); FMA2(a10, wB1, x0.y, a10);
            FMA2(a11, wA1, x1.x, a11); FMA2(a11, wB1, x1.y, a11);
            FMA2(a20, wA2, x0.x, a20); FMA2(a20, wB2, x0.y, a20);
            FMA2(a21, wA2, x1.x, a21); FMA2(a21, wB2, x1.y, a21);
            FMA2(a30, wA3, x0.x, a30); FMA2(a30, wB3, x0.y, a30);
            FMA2(a31, wA3, x1.x, a31); FMA2(a31, wB3, x1.y, a31);
        }
        if (c < nch - 1) {
            close_fast(sm, tid, cpos);
        } else {
            u64* spk = sm->spart + kg * 1024 + lane128;
            spk[0 * 128] = a00; spk[1 * 128] = a01;
            spk[2 * 128] = a10; spk[3 * 128] = a11;
            spk[4 * 128] = a20; spk[5 * 128] = a21;
            spk[6 * 128] = a30; spk[7 * 128] = a31;
            close_full(sm, tid, cpos, false);
        }
    }
    // Distributed reduce: 1024 outputs / 512 threads
    u64* const sp = sm->spart;
#pragma unroll
    for (int oi = 0; oi < 2; oi++) {
        const int o = tid + oi * 512;
        u64 v = sp[o];
        ADD2(v, v, sp[o + 1024]);
        ADD2(v, v, sp[o + 2048]);
        ADD2(v, v, sp[o + 3072]);
        const int c2i = o >> 7, l = o & 127;
        const int c = c2i >> 1, i = c2i & 1;
        const int col = (l >> 1) * 4 + c, rp = (l & 1) * 2 + i;
        const float b = sb[col];
        float v0, v1; UPK2(v0, v1, v);
        v0 = fmaxf(v0 + b, 0.f); v1 = fmaxf(v1 + b, 0.f);
        ((float2*)xout)[rp * XS + col] = make_float2(v0, v1);
    }
    __syncthreads();
}

// Output layer (N pad 128, K=256, chunk positions 10-11): KG=4 x CG=64(C=2)
// x RPH=2, streamed, fused Dopri5 epilogue.
__device__ __forceinline__ void out_stream(
    Smem* sm, const u64* __restrict__ xin,
    int s, int sub, int j, int row0, float* __restrict__ out,
    int tid, int kg, int lane128, bool last_stage) {
    const int cg = lane128 >> 1, rph = lane128 & 1;
    const int col0 = cg * 2;
    const int klocal0 = kg * 32;
    u64 a00 = 0, a01 = 0, a10 = 0, a11 = 0;
#pragma unroll
    for (int c = 0; c < 2; c++) {
        const int cpos = 10 + c;
        wait_full(sm, SCHED_BUF(cpos), SCHED_PAR(cpos));
        const float* wp = (const float*)sm->wbuf[SCHED_BUF(cpos)] + klocal0 * 128 + col0;
        const int xk = c * 128 + klocal0;
        const u64* xp0 = xin + (rph * 2)     * XS + xk;
        const u64* xp1 = xin + (rph * 2 + 1) * XS + xk;
#pragma unroll
        for (int kk = 0; kk < 32; kk += 2) {
            const float2 wA = *(const float2*)(wp + kk * 128);
            const float2 wB = *(const float2*)(wp + (kk + 1) * 128);
            u64 wA0, wA1, wB0, wB1;
            PK2(wA0, wA.x, wA.x); PK2(wA1, wA.y, wA.y);
            PK2(wB0, wB.x, wB.x); PK2(wB1, wB.y, wB.y);
            const ulonglong2 x0 = *(const ulonglong2*)(xp0 + kk);
            const ulonglong2 x1 = *(const ulonglong2*)(xp1 + kk);
            FMA2(a00, wA0, x0.x, a00); FMA2(a00, wB0, x0.y, a00);
            FMA2(a01, wA0, x1.x, a01); FMA2(a01, wB0, x1.y, a01);
            FMA2(a10, wA1, x0.x, a10); FMA2(a10, wB1, x0.y, a10);
            FMA2(a11, wA1, x1.x, a11); FMA2(a11, wB1, x1.y, a11);
        }
        if (c < 1) {
            if (last_stage) {
                const int barid = 1 + (cpos & 1);
                if (tid < 32)
                    asm volatile("bar.sync %0, %1;" :: "r"(barid), "r"(NTHR) : "memory");
                else
                    asm volatile("bar.arrive %0, %1;" :: "r"(barid), "r"(NTHR) : "memory");
            } else {
                close_fast(sm, tid, cpos);
            }
        } else {
            u64* spk = sm->spart + kg * 512 + lane128;
            spk[0 * 128] = a00; spk[1 * 128] = a01;
            spk[2 * 128] = a10; spk[3 * 128] = a11;
            close_full(sm, tid, cpos, last_stage);
        }
    }
    // Reduce + fused Dopri5 epilogue (one output per thread)
    u64* const sp = sm->spart;
    const int o = tid;
    u64 v = sp[o];
    ADD2(v, v, sp[o + 512]);
    ADD2(v, v, sp[o + 1024]);
    ADD2(v, v, sp[o + 1536]);
    const int row = o >> 7, lane = o & 127;
    const int cc = row >> 1, ii = row & 1;
    const int col = (lane >> 1) * 2 + cc, rp = (lane & 1) * 2 + ii;
    u64* const sks64 = sm->sks;
    u64* const sy64  = sm->sy;
    u64* const sxs64 = sm->sxs;
    const u64* const sacs64 = sm->sacs;

    if (col < OUT_) {
        const int o2 = rp * 128 + col;
        u64 bp; { const float b = sm->sb3[col]; PK2(bp, b, b); }
        u64 kn; ADD2(kn, v, bp);
        sks64[s * 512 + o2] = kn;
        const u64 y  = sy64[o2];
        const u64 hh = sm->shh2[rp];
        const u64 z = 0ull;
        if (s < 5) {
            u64 sum, ap;
            { const float a = cAT[s + 1][s]; PK2(ap, a, a); }
            FMA2(sum, ap, kn, z);
            for (int i2 = 0; i2 < s; i2++) {
                const float a = cAT[s + 1][i2]; PK2(ap, a, a);
                FMA2(sum, ap, sks64[i2 * 512 + o2], sum);
            }
            u64 x; FMA2(x, hh, sum, y);
            sxs64[rp * XS + col] = x;
        } else {
            u64 sum, ap;
            { const float a = cB[5]; PK2(ap, a, a); }
            FMA2(sum, ap, kn, z);
            { const float a = cB[4]; PK2(ap, a, a); FMA2(sum, ap, sks64[4 * 512 + o2], sum); }
            { const float a = cB[3]; PK2(ap, a, a); FMA2(sum, ap, sks64[3 * 512 + o2], sum); }
            { const float a = cB[2]; PK2(ap, a, a); FMA2(sum, ap, sks64[2 * 512 + o2], sum); }
            { const float a = cB[0]; PK2(ap, a, a); FMA2(sum, ap, sks64[0 * 512 + o2], sum); }
            u64 yn; FMA2(yn, hh, sum, y);
            sy64[o2] = yn;
            sxs64[rp * XS + col] = yn;
            if (sub == 1 && col < OB_) {
                float y0, y1; UPK2(y0, y1, yn);
                const size_t base = (size_t)(row0 + rp * 2) * T_ * OB_ +
                                    (size_t)(j + 1) * OB_ + col;
                out[base] = y0;
                out[base + (size_t)T_ * OB_] = y1;
            }
        }
    } else if (col < IN_) {
        const int s12n = (s < 5) ? (sub * 6 + s + 1) : ((sub == 0) ? 6 : -1);
        if (s12n >= 0)
            sxs64[rp * XS + col] = sacs64[s12n * 64 + rp * 16 + (col - OUT_)];
    }
    __syncthreads();
}

__global__ void __launch_bounds__(NTHR, 1)
node_kernel(const float* __restrict__ ob, const float* __restrict__ acs,
            const float* __restrict__ times,
            const float* __restrict__ b0, const float* __restrict__ b1,
            const float* __restrict__ b2, const float* __restrict__ b3,
            float* __restrict__ out) {
    extern __shared__ __align__(16) char smem_raw[];
    Smem* sm = reinterpret_cast<Smem*>(smem_raw);

    const int tid  = threadIdx.x;
    const int kg   = tid >> 7;
    const int l128 = tid & 127;
    const int row0 = blockIdx.x * R_;

    if (tid < 256) { sm->sb0[tid] = b0[tid]; sm->sb1[tid] = b1[tid]; sm->sb2[tid] = b2[tid]; }
    if (tid < OUT_) sm->sb3[tid] = b3[tid];
    sm->stimes[tid] = times[(size_t)(row0 + (tid >> 6)) * T_ + (tid & 63)];
    if (tid < 12) {
        const float* p;
        if      (tid < 2)  p = g_W0t + tid * 16384;
        else if (tid < 6)  p = g_W1t + (tid - 2) * 16384;
        else if (tid < 10) p = g_W2t + (tid - 6) * 16384;
        else               p = g_W3t + (tid - 10) * 16384;
        sm->srctab[tid] = (u64)p;
    }
    if (tid == 0) {
        uint32_t mb0 = smem_u32(&sm->mbar[0]);
        uint32_t mb1 = smem_u32(&sm->mbar[1]);
        asm volatile("mbarrier.init.shared.b64 [%0], 1;" :: "r"(mb0) : "memory");
        asm volatile("mbarrier.init.shared.b64 [%0], 1;" :: "r"(mb1) : "memory");
    }
    {
        const int col = tid & 127, rp = tid >> 7;
        const int r0 = row0 + rp * 2;
        float v0 = 0.f, v1 = 0.f;
        if (col < OB_) {
            v0 = ob[r0 * OB_ + col];
            v1 = ob[(r0 + 1) * OB_ + col];
            out[(size_t)r0 * T_ * OB_ + col] = v0;
            out[(size_t)(r0 + 1) * T_ * OB_ + col] = v1;
        }
        u64 p; PK2(p, v0, v1);
        sm->sy[tid] = p;
        if (col >= IN_) sm->sxs[rp * XS + col] = 0ull;
    }
    __syncthreads();

    if (tid == 0) { issue_chunk(sm, 0, 0); issue_chunk(sm, 1, 1); }

    for (int j = 0; j < T_ - 1; j++) {
        if (tid < 96) {
            const int s12 = tid >> 3, r = tid & 7;
            const float* tsr = &sm->stimes[r * 64];
            const float t0 = tsr[j], t1 = tsr[j + 1];
            const float h = (t1 - t0) / 2.0f;
            if (s12 == 0) sm->shh[r] = h;
            const int sub = (s12 >= 6) ? 1 : 0;
            const int s = s12 - sub * 6;
            const float t = t0 + (float)sub * h;
            float st;
            if      (s == 0) st = t;
            else if (s == 1) st = t + h / 5.0f;
            else if (s == 2) st = t + (3.0f * h) / 10.0f;
            else if (s == 3) st = t + (4.0f * h) / 5.0f;
            else if (s == 4) st = t + (8.0f * h) / 9.0f;
            else             st = t + h;
            int cnt = 0;
            for (int i = 0; i < T_; i++) cnt += (tsr[i] <= st) ? 1 : 0;
            int ai = cnt - 1;
            ai = max(0, min(ai, T_ - 1));
            sm->sidx[s12 * R_ + r] = ai;
        }
        __syncthreads();
        if (tid < RP_) {
            u64 p; PK2(p, sm->shh[tid * 2], sm->shh[tid * 2 + 1]);
            sm->shh2[tid] = p;
        }
        for (int idx = tid; idx < 12 * RP_ * AC_ * 2; idx += NTHR) {
            const int s12 = idx >> 7;
            const int rem = idx & 127;
            const int rp = rem >> 5, rem2 = rem & 31;
            const int c = rem2 >> 1, p = rem2 & 1, r = rp * 2 + p;
            ((float*)sm->sacs)[s12 * 128 + rp * 32 + c * 2 + p] =
                acs[(size_t)(row0 + r) * T_ * AC_ +
                    (size_t)sm->sidx[s12 * R_ + r] * AC_ + c];
        }
        __syncthreads();
        {
            const int col = tid & 127, rp = tid >> 7;
            if (col < OUT_)
                sm->sxs[rp * XS + col] = sm->sy[tid];
            else if (col < IN_)
                sm->sxs[rp * XS + col] = sm->sacs[rp * 16 + (col - OUT_)];
        }
        __syncthreads();

        for (int sub = 0; sub < 2; sub++) {
            for (int s = 0; s < 6; s++) {
                const bool last_stage = (j == T_ - 2) && (sub == 1) && (s == 5);
                hidden_stream(sm, 0, 2, sm->sxs, sm->sb0, sm->shA, tid, kg, l128);
                hidden_stream(sm, 2, 4, sm->shA, sm->sb1, sm->shB, tid, kg, l128);
                hidden_stream(sm, 6, 4, sm->shB, sm->sb2, sm->shA, tid, kg, l128);
                out_stream(sm, sm->shA, s, sub, j, row0, out,
                           tid, kg, l128, last_stage);
            }
        }
    }
}

extern "C" void kernel_launch(void* const* d_in, const int* in_sizes, int n_in,
                              void* d_out, int out_size) {
    const float* ob    = (const float*)d_in[0];
    const float* acs   = (const float*)d_in[1];
    const float* times = (const float*)d_in[2];
    const float* W0    = (const float*)d_in[3];
    const float* b0    = (const float*)d_in[4];
    const float* W1    = (const float*)d_in[5];
    const float* b1    = (const float*)d_in[6];
    const float* W2    = (const float*)d_in[7];
    const float* b2    = (const float*)d_in[8];
    const float* W3    = (const float*)d_in[9];
    const float* b3    = (const float*)d_in[10];
    float* out = (float*)d_out;

    cudaFuncSetAttribute(node_kernel,
                         cudaFuncAttributeMaxDynamicSharedMemorySize,
                         (int)sizeof(Smem));

    transpose_k<<<256, 256>>>(W0, W1, W2, W3);
    node_kernel<<<NCTA, NTHR, sizeof(Smem)>>>(ob, acs, times, b0, b1, b2, b3, out);
}